// round 13
// baseline (speedup 1.0000x reference)
#include <cuda_runtime.h>
#include <cuda_bf16.h>
#include <cstdint>

#define NT   256
#define NBLK 128
#define SEQ  512

#if defined(__CUDA_ARCH_FEAT_SM103_ALL)
#define TC_PATH 1
#else
#define TC_PATH 0
#endif

// host-side smem size = max(fma path 228096, tc path 83968)
#define SM_BYTES_HOST 228096

typedef unsigned long long u64;

// ---------------- shared helpers (both paths) ----------------
static __device__ __forceinline__ float sigf(float x) {
    return __fdividef(1.f, 1.f + __expf(-x));
}
static __device__ __forceinline__ float tanhf_(float x) {
    float xx = fmaxf(x, -30.f);
    float e  = __expf(-2.f * xx);
    return __fdividef(1.f - e, 1.f + e);
}

extern __shared__ char smraw[];

#if TC_PATH
// ================= tcgen05 path =================
#define IDESC 0x8080490u  // f16 MMA: F32 acc, bf16 a/b, M=128, N=32

#define SB_MBAR  0
#define SB_TMEMP 16
#define FI_WI1 8
#define FI_B1  264
#define FI_B2  520
#define FI_XT  776            // 16 x 36
#define FI_H2F 1352           // 32 x 66
#define FI_ZB  3464           // 256 x 36
#define SB_T0  51200          // 8 bf16 tiles x 4KB (SW128 32x128B)
// tile order: H1A_hi,H1A_lo,H1B_hi,H1B_lo,H2A_hi,H2A_lo,H2B_hi,H2B_lo

static __device__ __forceinline__ uint32_t smem_u32(const void* p) {
    uint32_t a;
    asm("{ .reg .u64 t; cvta.to.shared.u64 t, %1; cvt.u32.u64 %0, t; }" : "=r"(a) : "l"(p));
    return a;
}
static __device__ __forceinline__ uint32_t elect1() {
    uint32_t p;
    asm volatile("{ .reg .pred p; elect.sync _|p, 0xFFFFFFFF; selp.b32 %0,1,0,p; }" : "=r"(p));
    return p;
}
static __device__ __forceinline__ uint64_t mkdesc(uint32_t sa) {
    const uint64_t base = (2ULL << 61) | (1ULL << 46) | (64ULL << 32) | (1ULL << 16);
    return base | ((uint64_t)(sa >> 4) & 0x3FFF);
}
static __device__ __forceinline__ void mma_ts(uint32_t d, uint32_t a, uint64_t bd) {
    asm volatile("{ .reg .pred p; setp.eq.u32 p,1,1;\n\t"
        "tcgen05.mma.cta_group::1.kind::f16 [%0], [%1], %2, %3, {%4,%4,%4,%4}, p; }"
        :: "r"(d), "r"(a), "l"(bd), "r"(IDESC), "r"(0u) : "memory");
}
#define TC_ALLOC(sa,n)  asm volatile("tcgen05.alloc.cta_group::1.sync.aligned.shared::cta.b32 [%0], %1;" :: "r"(sa), "r"(n) : "memory")
#define TC_DEALLOC(t,n) asm volatile("tcgen05.dealloc.cta_group::1.sync.aligned.b32 %0, %1;" :: "r"(t), "r"(n))
#define TC_RELINQ()     asm volatile("tcgen05.relinquish_alloc_permit.cta_group::1.sync.aligned;")
#define TC_WST()        asm volatile("tcgen05.wait::st.sync.aligned;" ::: "memory")
#define TC_WLD()        asm volatile("tcgen05.wait::ld.sync.aligned;" ::: "memory")
#define TC_FB()         asm volatile("tcgen05.fence::before_thread_sync;" ::: "memory")
#define TC_FA()         asm volatile("tcgen05.fence::after_thread_sync;" ::: "memory")
#define TC_COMMIT(mb)   asm volatile("tcgen05.commit.cta_group::1.mbarrier::arrive::one.shared::cluster.b64 [%0];" :: "r"(mb) : "memory")
#define FENCE_ASYNC()   asm volatile("fence.proxy.async.shared::cta;" ::: "memory")
#define MBAR_INIT(mb,n) asm volatile("mbarrier.init.shared.b64 [%0], %1;" :: "r"(mb), "r"(n) : "memory")
#define MBAR_WAIT(mb,par) do { uint32_t _m=(mb),_p=(par),_d; \
    asm volatile("{ .reg .pred p; mbarrier.try_wait.parity.acquire.cta.shared::cta.b64 p, [%1], %2; selp.b32 %0,1,0,p; }" : "=r"(_d) : "r"(_m), "r"(_p) : "memory"); \
    if (!_d) asm volatile("{ .reg .pred P1; WL%=: mbarrier.try_wait.parity.acquire.cta.shared::cta.b64 P1, [%0], %1, 0x989680; @P1 bra.uni WD%=; bra.uni WL%=; WD%=: }" :: "r"(_m), "r"(_p) : "memory"); \
    } while (0)

#define R32(r) "r"((r)[0]),"r"((r)[1]),"r"((r)[2]),"r"((r)[3]),"r"((r)[4]),"r"((r)[5]),"r"((r)[6]),"r"((r)[7]),\
"r"((r)[8]),"r"((r)[9]),"r"((r)[10]),"r"((r)[11]),"r"((r)[12]),"r"((r)[13]),"r"((r)[14]),"r"((r)[15]),\
"r"((r)[16]),"r"((r)[17]),"r"((r)[18]),"r"((r)[19]),"r"((r)[20]),"r"((r)[21]),"r"((r)[22]),"r"((r)[23]),\
"r"((r)[24]),"r"((r)[25]),"r"((r)[26]),"r"((r)[27]),"r"((r)[28]),"r"((r)[29]),"r"((r)[30]),"r"((r)[31])
#define W32(r) "=r"((r)[0]),"=r"((r)[1]),"=r"((r)[2]),"=r"((r)[3]),"=r"((r)[4]),"=r"((r)[5]),"=r"((r)[6]),"=r"((r)[7]),\
"=r"((r)[8]),"=r"((r)[9]),"=r"((r)[10]),"=r"((r)[11]),"=r"((r)[12]),"=r"((r)[13]),"=r"((r)[14]),"=r"((r)[15]),\
"=r"((r)[16]),"=r"((r)[17]),"=r"((r)[18]),"=r"((r)[19]),"=r"((r)[20]),"=r"((r)[21]),"=r"((r)[22]),"=r"((r)[23]),\
"=r"((r)[24]),"=r"((r)[25]),"=r"((r)[26]),"=r"((r)[27]),"=r"((r)[28]),"=r"((r)[29]),"=r"((r)[30]),"=r"((r)[31])

#define STTM32(a, r) asm volatile("tcgen05.st.sync.aligned.32x32b.x32.b32 [%0], {%1,%2,%3,%4,%5,%6,%7,%8,%9,%10,%11,%12,%13,%14,%15,%16,%17,%18,%19,%20,%21,%22,%23,%24,%25,%26,%27,%28,%29,%30,%31,%32};" :: "r"(a), R32(r) : "memory")
#define LDTM32(r, a) asm volatile("tcgen05.ld.sync.aligned.32x32b.x32.b32 {%0,%1,%2,%3,%4,%5,%6,%7,%8,%9,%10,%11,%12,%13,%14,%15,%16,%17,%18,%19,%20,%21,%22,%23,%24,%25,%26,%27,%28,%29,%30,%31}, [%32];" : W32(r) : "r"(a))

static __device__ __forceinline__ void a_row(const float* g, uint32_t thi, uint32_t tlo) {
    uint32_t whi[32], wlo[32];
    #pragma unroll
    for (int i = 0; i < 32; ++i) {
        float a = g[2 * i], b = g[2 * i + 1];
        __nv_bfloat16 ah = __float2bfloat16(a), bh = __float2bfloat16(b);
        __nv_bfloat16 al = __float2bfloat16(a - __bfloat162float(ah));
        __nv_bfloat16 bl = __float2bfloat16(b - __bfloat162float(bh));
        whi[i] = (uint32_t)__bfloat16_as_ushort(ah) | ((uint32_t)__bfloat16_as_ushort(bh) << 16);
        wlo[i] = (uint32_t)__bfloat16_as_ushort(al) | ((uint32_t)__bfloat16_as_ushort(bl) << 16);
    }
    STTM32(thi, whi); STTM32(tlo, wlo);
}

static __device__ __forceinline__ void mma_block(uint32_t tb, uint32_t dbase,
        uint32_t ahi, uint32_t alo, uint64_t dh, uint64_t dl) {
    #pragma unroll
    for (int tl = 0; tl < 2; ++tl) {
        uint32_t d = tb + dbase + tl * 32, ah = tb + ahi + tl * 32, al = tb + alo + tl * 32;
        #pragma unroll
        for (int kc = 0; kc < 4; ++kc) {
            mma_ts(d, ah + kc * 8, dh + kc * 2);
            mma_ts(d, al + kc * 8, dh + kc * 2);
            mma_ts(d, ah + kc * 8, dl + kc * 2);
        }
    }
}

static __device__ __forceinline__ void z_out(float* smf, uint32_t addr, int grow) {
    uint32_t zr[32];
    LDTM32(zr, addr);
    TC_WLD();
    float* zp = smf + FI_ZB + grow * 36;
    #pragma unroll
    for (int q = 0; q < 8; ++q)
        *(float4*)&zp[4 * q] = make_float4(__uint_as_float(zr[4 * q]),
            __uint_as_float(zr[4 * q + 1]), __uint_as_float(zr[4 * q + 2]),
            __uint_as_float(zr[4 * q + 3]));
}

static __device__ __forceinline__ void pw(float* smf, int hid, int bq, float* c,
                                          char* bhi, char* blo, float* hf) {
    const float* zb = smf + FI_ZB + bq * 8;
    float zi[8], zf[8], zg[8], zo[8];
    *(float4*)&zi[0] = *(const float4*)&zb[hid * 36];
    *(float4*)&zi[4] = *(const float4*)&zb[hid * 36 + 4];
    *(float4*)&zf[0] = *(const float4*)&zb[(64 + hid) * 36];
    *(float4*)&zf[4] = *(const float4*)&zb[(64 + hid) * 36 + 4];
    *(float4*)&zg[0] = *(const float4*)&zb[(128 + hid) * 36];
    *(float4*)&zg[4] = *(const float4*)&zb[(128 + hid) * 36 + 4];
    *(float4*)&zo[0] = *(const float4*)&zb[(192 + hid) * 36];
    *(float4*)&zo[4] = *(const float4*)&zb[(192 + hid) * 36 + 4];
    #pragma unroll
    for (int j = 0; j < 8; ++j) {
        float cc = sigf(zf[j]) * c[j] + sigf(zi[j]) * tanhf_(zg[j]);
        c[j] = cc;
        float h = sigf(zo[j]) * tanhf_(cc);
        int b = bq * 8 + j;
        __nv_bfloat16 hh = __float2bfloat16(h);
        __nv_bfloat16 hl = __float2bfloat16(h - __bfloat162float(hh));
        int off = b * 128 + hid * 2, sw = off ^ ((off >> 3) & 0x70);
        *(__nv_bfloat16*)(bhi + sw) = hh;
        *(__nv_bfloat16*)(blo + sw) = hl;
        if (hf) hf[b * 66 + hid] = h;
    }
}
#else
// ================= FMA fallback helpers =================
static __device__ __forceinline__ u64 splat2f(float v) {
    u64 r; unsigned u = __float_as_uint(v);
    asm("mov.b64 %0, {%1, %1};" : "=l"(r) : "r"(u));
    return r;
}
static __device__ __forceinline__ u64 pack2f(float a, float b) {
    u64 r; unsigned ua = __float_as_uint(a), ub = __float_as_uint(b);
    asm("mov.b64 %0, {%1, %2};" : "=l"(r) : "r"(ua), "r"(ub));
    return r;
}
static __device__ __forceinline__ void fma2(u64& d, u64 a, u64 b) {
    asm("fma.rn.f32x2 %0, %1, %2, %0;" : "+l"(d) : "l"(a), "l"(b));
}
static __device__ __forceinline__ float lo32(u64 v) { return __uint_as_float((unsigned)v); }
static __device__ __forceinline__ float hi32(u64 v) { return __uint_as_float((unsigned)(v >> 32)); }

// smem float offsets (fallback)
#define WT1_O 0
#define WT2_O (WT1_O + 64 * 256)
#define HA_O  (WT2_O + 128 * 256)
#define XT_O  (HA_O + 128 * 32)
#define B1_O  (XT_O + 64 * 34)
#define B2_O  (B1_O + 256)
#define WI1_O (B2_O + 256)
#define HW_O  (WI1_O + 256)

static __device__ __forceinline__ void pointwise_f(const u64 acc[4][4], float c[8], float* hdst) {
    float hv[8];
    #pragma unroll
    for (int p = 0; p < 4; ++p) {
        #pragma unroll
        for (int q = 0; q < 2; ++q) {
            int j = 2 * p + q;
            float zi = q ? hi32(acc[0][p]) : lo32(acc[0][p]);
            float zf = q ? hi32(acc[1][p]) : lo32(acc[1][p]);
            float zg = q ? hi32(acc[2][p]) : lo32(acc[2][p]);
            float zo = q ? hi32(acc[3][p]) : lo32(acc[3][p]);
            float cc = sigf(zf) * c[j] + sigf(zi) * tanhf_(zg);
            c[j] = cc;
            hv[j] = sigf(zo) * tanhf_(cc);
        }
    }
    *(float4*)&hdst[0] = make_float4(hv[0], hv[1], hv[2], hv[3]);
    *(float4*)&hdst[4] = make_float4(hv[4], hv[5], hv[6], hv[7]);
}

#define LOADK(K, b) { \
    int ha = HA_O + ((K) << 5) + (((bg + (K)) & 3) << 3); \
    ulonglong2 q0 = *(const ulonglong2*)&sm[ha]; \
    ulonglong2 q1 = *(const ulonglong2*)&sm[ha + 4]; \
    ulonglong2 q2 = *(const ulonglong2*)&sm[ha + 2048]; \
    ulonglong2 q3 = *(const ulonglong2*)&sm[ha + 2048 + 4]; \
    h1r[b][0] = q0.x; h1r[b][1] = q0.y; h1r[b][2] = q1.x; h1r[b][3] = q1.y; \
    h2r[b][0] = q2.x; h2r[b][1] = q2.y; h2r[b][2] = q3.x; h2r[b][3] = q3.y; \
    w1r[b]  = *(const float4*)&sm[WT1_O + (K) * 256 + hid4]; \
    w2ar[b] = *(const float4*)&sm[WT2_O + (K) * 256 + hid4]; \
    w2br[b] = *(const float4*)&sm[WT2_O + ((K) + 64) * 256 + hid4]; }

#define FMA_G(g, wv, accarr, hparr) { \
    u64 s = splat2f(wv); \
    fma2(accarr[g][0], s, hparr[0]); fma2(accarr[g][1], s, hparr[1]); \
    fma2(accarr[g][2], s, hparr[2]); fma2(accarr[g][3], s, hparr[3]); }

#define FMAK(b) { \
    FMA_G(0, w1r[b].x,  acc1, h1r[b]); FMA_G(1, w1r[b].y,  acc1, h1r[b]); \
    FMA_G(2, w1r[b].z,  acc1, h1r[b]); FMA_G(3, w1r[b].w,  acc1, h1r[b]); \
    FMA_G(0, w2ar[b].x, acc2, h1r[b]); FMA_G(1, w2ar[b].y, acc2, h1r[b]); \
    FMA_G(2, w2ar[b].z, acc2, h1r[b]); FMA_G(3, w2ar[b].w, acc2, h1r[b]); \
    FMA_G(0, w2br[b].x, acc2, h2r[b]); FMA_G(1, w2br[b].y, acc2, h2r[b]); \
    FMA_G(2, w2br[b].z, acc2, h2r[b]); FMA_G(3, w2br[b].w, acc2, h2r[b]); }
#endif

__global__ void __launch_bounds__(NT, 1)
lstm_kernel(const float* __restrict__ x,
            const float* __restrict__ W_ih1, const float* __restrict__ W_hh1,
            const float* __restrict__ b_ih1, const float* __restrict__ b_hh1,
            const float* __restrict__ W_ih2, const float* __restrict__ W_hh2,
            const float* __restrict__ b_ih2, const float* __restrict__ b_hh2,
            const float* __restrict__ W_d1, const float* __restrict__ b_d1,
            const float* __restrict__ W_d2, const float* __restrict__ b_d2,
            float* __restrict__ out)
{
#if TC_PATH
    char* smc = smraw;
    float* smf = (float*)smc;
    const int tid = threadIdx.x, lane = tid & 31, wrp = tid >> 5;
    const int wg = wrp >> 2, sub = wrp & 3;
    const int grow = wg * 128 + sub * 32 + lane;
    const int b0 = blockIdx.x * 32;
    const uint32_t sbase = smem_u32(smc);
    const uint32_t woff = (uint32_t)sub << 21;
    const uint32_t mb1 = sbase + SB_MBAR, mb2 = sbase + SB_MBAR + 8;

    if (wrp == 0) TC_ALLOC(sbase + SB_TMEMP, 512);
    __syncthreads();
    uint32_t tb;
    asm volatile("ld.shared.b32 %0, [%1];" : "=r"(tb) : "r"(sbase + SB_TMEMP));
    if (tid == 0) { MBAR_INIT(mb1, 1); MBAR_INIT(mb2, 1); }

    for (int i = tid; i < 256; i += NT) {
        smf[FI_WI1 + i] = W_ih1[i];
        smf[FI_B1 + i] = b_ih1[i] + b_hh1[i];
        smf[FI_B2 + i] = b_ih2[i] + b_hh2[i];
    }
    for (int i = tid; i < 8192; i += NT) ((uint32_t*)(smc + SB_T0))[i] = 0;

    a_row(W_hh1 + grow * 64, tb + 128 + wg * 32 + woff, tb + 192 + wg * 32 + woff);
    a_row(W_ih2 + grow * 64, tb + 256 + wg * 32 + woff, tb + 320 + wg * 32 + woff);
    a_row(W_hh2 + grow * 64, tb + 384 + wg * 32 + woff, tb + 448 + wg * 32 + woff);
    TC_WST();
    TC_FB();
    FENCE_ASYNC();
    __syncthreads();

    uint64_t dt[8];
    #pragma unroll
    for (int i = 0; i < 8; ++i) dt[i] = mkdesc(sbase + SB_T0 + i * 4096);

    float c1[8], c2[8];
    #pragma unroll
    for (int j = 0; j < 8; ++j) { c1[j] = 0.f; c2[j] = 0.f; }
    const int hid = tid & 63, bq = tid >> 6;
    const float wi = smf[FI_WI1 + grow], bb1 = smf[FI_B1 + grow], bb2 = smf[FI_B2 + grow];

    for (int t = 0; t < SEQ; ++t) {
        if ((t & 15) == 0) {
            for (int i = tid; i < 512; i += NT) {
                int row = i >> 4, tq = i & 15;
                smf[FI_XT + tq * 36 + row] = x[(size_t)(b0 + row) * SEQ + t + tq];
            }
            __syncthreads();
        }
        const int tt = t & 15, ph = t & 1;
        const int h1c = ph ? 2 : 0, h1p = ph ? 0 : 2;
        const int h2c = ph ? 6 : 4, h2p = ph ? 4 : 6;

        // A: D init (fp32 exact bias + x*w_ih1)
        {
            uint32_t r1[32], r2[32];
            #pragma unroll
            for (int q = 0; q < 8; ++q) {
                float4 xv = *(const float4*)&smf[FI_XT + tt * 36 + 4 * q];
                r1[4 * q + 0] = __float_as_uint(fmaf(xv.x, wi, bb1));
                r1[4 * q + 1] = __float_as_uint(fmaf(xv.y, wi, bb1));
                r1[4 * q + 2] = __float_as_uint(fmaf(xv.z, wi, bb1));
                r1[4 * q + 3] = __float_as_uint(fmaf(xv.w, wi, bb1));
            }
            #pragma unroll
            for (int q = 0; q < 32; ++q) r2[q] = __float_as_uint(bb2);
            STTM32(tb + 0 + wg * 32 + woff, r1);
            STTM32(tb + 64 + wg * 32 + woff, r2);
            TC_WST();
        }
        TC_FB();
        __syncthreads();

        // B: L1 MMAs (commit mb1) + L2*h2prev MMAs (queued)
        if (wrp == 0) {
            TC_FA();
            if (elect1()) {
                mma_block(tb, 0, 128, 192, dt[h1p], dt[h1p + 1]);
                TC_COMMIT(mb1);
                mma_block(tb, 64, 384, 448, dt[h2p], dt[h2p + 1]);
            }
        }

        // C: z1
        MBAR_WAIT(mb1, ph);
        TC_FA();
        z_out(smf, tb + wg * 32, grow);
        __syncthreads();

        // D: PW1 -> h1 cur
        pw(smf, hid, bq, c1, smc + SB_T0 + h1c * 4096, smc + SB_T0 + (h1c + 1) * 4096, nullptr);
        FENCE_ASYNC();
        __syncthreads();

        // E: L2*h1cur MMAs (commit mb2)
        if (wrp == 0) {
            TC_FA();
            if (elect1()) {
                mma_block(tb, 64, 256, 320, dt[h1c], dt[h1c + 1]);
                TC_COMMIT(mb2);
            }
        }

        // F: z2
        MBAR_WAIT(mb2, ph);
        TC_FA();
        z_out(smf, tb + 64 + wg * 32, grow);
        __syncthreads();

        // G: PW2 -> h2 cur
        pw(smf, hid, bq, c2, smc + SB_T0 + h2c * 4096, smc + SB_T0 + (h2c + 1) * 4096,
           (t == SEQ - 1) ? &smf[FI_H2F] : nullptr);
        FENCE_ASYNC();
        __syncthreads();
    }

    if (wrp == 0) { TC_RELINQ(); TC_DEALLOC(tb, 512); }

    // dense head on fp32 h2[511]
    for (int i = tid; i < 2048; i += NT) smf[FI_ZB + i] = W_d1[i];
    for (int i = tid; i < 768; i += NT) smf[FI_ZB + 2048 + i] = W_d2[i];
    if (tid < 32) smf[FI_ZB + 2816 + tid] = b_d1[tid];
    if (tid < 24) smf[FI_ZB + 2848 + tid] = b_d2[tid];
    __syncthreads();

    for (int idx = tid; idx < 1024; idx += NT) {
        int b = idx >> 5, j = idx & 31;
        float a = smf[FI_ZB + 2816 + j];
        #pragma unroll 8
        for (int k = 0; k < 64; ++k)
            a += smf[FI_H2F + b * 66 + k] * smf[FI_ZB + j * 64 + k];
        smf[FI_ZB + 2880 + b * 32 + j] = fmaxf(a, 0.f);
    }
    __syncthreads();
    for (int idx = tid; idx < 768; idx += NT) {
        int b = idx / 24, o = idx - b * 24;
        float a = smf[FI_ZB + 2848 + o];
        #pragma unroll 8
        for (int j = 0; j < 32; ++j)
            a += smf[FI_ZB + 2880 + b * 32 + j] * smf[FI_ZB + 2048 + o * 32 + j];
        out[(size_t)(b0 + b) * 24 + o] = a;
    }
#else
    // ================= FMA fallback (R4, 4786us) =================
    float* sm = (float*)smraw;
    const int tid  = threadIdx.x;
    const int lane = tid & 31;
    const int wrp  = tid >> 5;
    const int hid  = ((wrp & 1) << 5) | lane;
    const int bg   = wrp >> 1;
    const int b0   = blockIdx.x * 32;
    const int octh = ((bg + hid) & 3) << 3;
    const int hid4 = hid << 2;

    for (int i = tid; i < 64 * 256; i += NT) {
        int k = i >> 8, r = i & 255;
        int g = r >> 6, h = r & 63;
        sm[WT1_O + k * 256 + h * 4 + g] = W_hh1[r * 64 + k];
    }
    for (int i = tid; i < 64 * 256; i += NT) {
        int k = i >> 8, r = i & 255;
        int g = r >> 6, h = r & 63;
        sm[WT2_O + k * 256 + h * 4 + g] = W_ih2[r * 64 + k];
    }
    for (int i = tid; i < 64 * 256; i += NT) {
        int k = i >> 8, r = i & 255;
        int g = r >> 6, h = r & 63;
        sm[WT2_O + (64 + k) * 256 + h * 4 + g] = W_hh2[r * 64 + k];
    }
    for (int i = tid; i < 256; i += NT) {
        sm[B1_O + i]  = b_ih1[i] + b_hh1[i];
        sm[B2_O + i]  = b_ih2[i] + b_hh2[i];
        sm[WI1_O + i] = W_ih1[i];
    }
    for (int i = tid; i < 128 * 32; i += NT) sm[HA_O + i] = 0.f;
    {
        #pragma unroll
        for (int it = 0; it < 2; ++it) {
            int i = tid + it * NT;
            int row = i >> 4, q = (i & 15) << 2;
            float4 v = *(const float4*)(x + (size_t)(b0 + row) * SEQ + q);
            sm[XT_O + (q + 0) * 34 + row] = v.x;
            sm[XT_O + (q + 1) * 34 + row] = v.y;
            sm[XT_O + (q + 2) * 34 + row] = v.z;
            sm[XT_O + (q + 3) * 34 + row] = v.w;
        }
    }
    __syncthreads();

    u64   acc1[4][4], acc2[4][4];
    float c1[8], c2[8];
    #pragma unroll
    for (int j = 0; j < 8; ++j) { c1[j] = 0.f; c2[j] = 0.f; }

    float* h1dst = &sm[HA_O + hid * 32 + octh];
    float* h2dst = &sm[HA_O + (64 + hid) * 32 + octh];

    {
        u64 xp[4];
        #pragma unroll
        for (int p = 0; p < 4; ++p)
            xp[p] = *(const u64*)&sm[XT_O + 0 * 34 + bg * 8 + 2 * p];
        #pragma unroll
        for (int g = 0; g < 4; ++g) {
            u64 sb = splat2f(sm[B1_O + g * 64 + hid]);
            u64 sw = splat2f(sm[WI1_O + g * 64 + hid]);
            #pragma unroll
            for (int p = 0; p < 4; ++p) { acc1[g][p] = sb; fma2(acc1[g][p], sw, xp[p]); }
        }
        pointwise_f(acc1, c1, h1dst);
    }
    __syncthreads();

    for (int t = 0; t < SEQ; ++t) {
        if (((t + 1) & 63) == 0 && (t + 1) < SEQ) {
            int base = t + 1;
            #pragma unroll
            for (int it = 0; it < 2; ++it) {
                int i = tid + it * NT;
                int row = i >> 4, q = (i & 15) << 2;
                float4 v = *(const float4*)(x + (size_t)(b0 + row) * SEQ + base + q);
                sm[XT_O + (q + 0) * 34 + row] = v.x;
                sm[XT_O + (q + 1) * 34 + row] = v.y;
                sm[XT_O + (q + 2) * 34 + row] = v.z;
                sm[XT_O + (q + 3) * 34 + row] = v.w;
            }
            __syncthreads();
        }
        const int tt = ((t + 1) < SEQ ? (t + 1) : t) & 63;

        #pragma unroll
        for (int g = 0; g < 4; ++g) {
            u64 s = splat2f(sm[B2_O + g * 64 + hid]);
            #pragma unroll
            for (int p = 0; p < 4; ++p) acc2[g][p] = s;
        }
        {
            u64 xp[4];
            #pragma unroll
            for (int p = 0; p < 4; ++p)
                xp[p] = *(const u64*)&sm[XT_O + tt * 34 + bg * 8 + 2 * p];
            #pragma unroll
            for (int g = 0; g < 4; ++g) {
                u64 sb = splat2f(sm[B1_O + g * 64 + hid]);
                u64 sw = splat2f(sm[WI1_O + g * 64 + hid]);
                #pragma unroll
                for (int p = 0; p < 4; ++p) { acc1[g][p] = sb; fma2(acc1[g][p], sw, xp[p]); }
            }
        }

        {
            u64 h1r[2][4], h2r[2][4];
            float4 w1r[2], w2ar[2], w2br[2];
            LOADK(0, 0);
            #pragma unroll 2
            for (int k = 0; k < 64; ++k) {
                const int cur = k & 1;
                if (k < 63) LOADK(k + 1, cur ^ 1);
                FMAK(cur);
            }
        }
        __syncthreads();

        pointwise_f(acc2, c2, h2dst);
        if (t + 1 < SEQ) pointwise_f(acc1, c1, h1dst);
        __syncthreads();
    }

    for (int i = tid; i < 32 * 64; i += NT) sm[XT_O + i] = W_d1[i];
    for (int i = tid; i < 24 * 32; i += NT) sm[HW_O + i] = W_d2[i];
    if (tid < 32) sm[HW_O + 768 + tid] = b_d1[tid];
    if (tid < 24) sm[HW_O + 800 + tid] = b_d2[tid];
    __syncthreads();

    for (int idx = tid; idx < 32 * 32; idx += NT) {
        int b = idx >> 5, j = idx & 31;
        int ob = b >> 3, bl = b & 7;
        float a = sm[HW_O + 768 + j];
        #pragma unroll 8
        for (int k = 0; k < 64; ++k) {
            float hv = sm[HA_O + (64 + k) * 32 + (((ob + k) & 3) << 3) + bl];
            a += hv * sm[XT_O + j * 64 + k];
        }
        sm[HA_O + b * 32 + j] = fmaxf(a, 0.f);
    }
    __syncthreads();
    for (int idx = tid; idx < 32 * 24; idx += NT) {
        int b = idx / 24, o = idx - b * 24;
        float a = sm[HW_O + 800 + o];
        #pragma unroll 8
        for (int j = 0; j < 32; ++j)
            a += sm[HA_O + b * 32 + j] * sm[HW_O + o * 32 + j];
        out[(size_t)(b0 + b) * 24 + o] = a;
    }
#endif
}

extern "C" void kernel_launch(void* const* d_in, const int* in_sizes, int n_in,
                              void* d_out, int out_size)
{
    const float* x     = (const float*)d_in[0];
    const float* W_ih1 = (const float*)d_in[1];
    const float* W_hh1 = (const float*)d_in[2];
    const float* b_ih1 = (const float*)d_in[3];
    const float* b_hh1 = (const float*)d_in[4];
    const float* W_ih2 = (const float*)d_in[5];
    const float* W_hh2 = (const float*)d_in[6];
    const float* b_ih2 = (const float*)d_in[7];
    const float* b_hh2 = (const float*)d_in[8];
    const float* W_d1  = (const float*)d_in[9];
    const float* b_d1  = (const float*)d_in[10];
    const float* W_d2  = (const float*)d_in[11];
    const float* b_d2  = (const float*)d_in[12];
    float* out = (float*)d_out;

    cudaFuncSetAttribute(lstm_kernel,
                         cudaFuncAttributeMaxDynamicSharedMemorySize, SM_BYTES_HOST);
    lstm_kernel<<<NBLK, NT, SM_BYTES_HOST>>>(
        x, W_ih1, W_hh1, b_ih1, b_hh1, W_ih2, W_hh2, b_ih2, b_hh2,
        W_d1, b_d1, W_d2, b_d2, out);
}

// round 14
// speedup vs baseline: 1.0012x; 1.0012x over previous
#include <cuda_runtime.h>
#include <cuda_bf16.h>
#include <cstdint>

#define NT   256
#define NBLK 128
#define SEQ  512

#if defined(__CUDA_ARCH_FEAT_SM103_ALL)
#define TC_PATH 1
#else
#define TC_PATH 0
#endif

// host-side smem size = max(fma path 228096, tc path 83968)
#define SM_BYTES_HOST 228096

typedef unsigned long long u64;

// ---------------- shared helpers (both paths) ----------------
static __device__ __forceinline__ float sigf(float x) {
    return __fdividef(1.f, 1.f + __expf(-x));
}
static __device__ __forceinline__ float tanhf_(float x) {
    float xx = fmaxf(x, -30.f);
    float e  = __expf(-2.f * xx);
    return __fdividef(1.f - e, 1.f + e);
}

extern __shared__ char smraw[];

#if TC_PATH
// ================= tcgen05 path =================
#define IDESC 0x8080490u  // f16 MMA: F32 acc, bf16 a/b, M=128, N=32

#define SB_MBAR  0
#define SB_TMEMP 16
#define FI_WI1 8
#define FI_B1  264
#define FI_B2  520
#define FI_XT  776            // 16 x 36
#define FI_H2F 1352           // 32 x 66
#define FI_ZB  3464           // 256 x 36
#define SB_T0  51200          // 8 bf16 tiles x 4KB (SW128 32x128B)
// tile order: H1A_hi,H1A_lo,H1B_hi,H1B_lo,H2A_hi,H2A_lo,H2B_hi,H2B_lo

static __device__ __forceinline__ uint32_t smem_u32(const void* p) {
    uint32_t a;
    asm("{ .reg .u64 t; cvta.to.shared.u64 t, %1; cvt.u32.u64 %0, t; }" : "=r"(a) : "l"(p));
    return a;
}
static __device__ __forceinline__ uint32_t elect1() {
    uint32_t p;
    asm volatile("{ .reg .pred p; elect.sync _|p, 0xFFFFFFFF; selp.b32 %0,1,0,p; }" : "=r"(p));
    return p;
}
static __device__ __forceinline__ uint64_t mkdesc(uint32_t sa) {
    const uint64_t base = (2ULL << 61) | (1ULL << 46) | (64ULL << 32) | (1ULL << 16);
    return base | ((uint64_t)(sa >> 4) & 0x3FFF);
}
static __device__ __forceinline__ void mma_ts(uint32_t d, uint32_t a, uint64_t bd) {
    asm volatile("{ .reg .pred p; setp.eq.u32 p,1,1;\n\t"
        "tcgen05.mma.cta_group::1.kind::f16 [%0], [%1], %2, %3, {%4,%4,%4,%4}, p; }"
        :: "r"(d), "r"(a), "l"(bd), "r"(IDESC), "r"(0u) : "memory");
}
#define TC_ALLOC(sa,n)  asm volatile("tcgen05.alloc.cta_group::1.sync.aligned.shared::cta.b32 [%0], %1;" :: "r"(sa), "r"(n) : "memory")
#define TC_DEALLOC(t,n) asm volatile("tcgen05.dealloc.cta_group::1.sync.aligned.b32 %0, %1;" :: "r"(t), "r"(n))
#define TC_RELINQ()     asm volatile("tcgen05.relinquish_alloc_permit.cta_group::1.sync.aligned;")
#define TC_WST()        asm volatile("tcgen05.wait::st.sync.aligned;" ::: "memory")
#define TC_WLD()        asm volatile("tcgen05.wait::ld.sync.aligned;" ::: "memory")
#define TC_FB()         asm volatile("tcgen05.fence::before_thread_sync;" ::: "memory")
#define TC_FA()         asm volatile("tcgen05.fence::after_thread_sync;" ::: "memory")
#define TC_COMMIT(mb)   asm volatile("tcgen05.commit.cta_group::1.mbarrier::arrive::one.shared::cluster.b64 [%0];" :: "r"(mb) : "memory")
#define FENCE_ASYNC()   asm volatile("fence.proxy.async.shared::cta;" ::: "memory")
#define MBAR_INIT(mb,n) asm volatile("mbarrier.init.shared.b64 [%0], %1;" :: "r"(mb), "r"(n) : "memory")
#define MBAR_WAIT(mb,par) do { uint32_t _m=(mb),_p=(par),_d; \
    asm volatile("{ .reg .pred p; mbarrier.try_wait.parity.acquire.cta.shared::cta.b64 p, [%1], %2; selp.b32 %0,1,0,p; }" : "=r"(_d) : "r"(_m), "r"(_p) : "memory"); \
    if (!_d) asm volatile("{ .reg .pred P1; WL%=: mbarrier.try_wait.parity.acquire.cta.shared::cta.b64 P1, [%0], %1, 0x989680; @P1 bra.uni WD%=; bra.uni WL%=; WD%=: }" :: "r"(_m), "r"(_p) : "memory"); \
    } while (0)

#define R32(r) "r"((r)[0]),"r"((r)[1]),"r"((r)[2]),"r"((r)[3]),"r"((r)[4]),"r"((r)[5]),"r"((r)[6]),"r"((r)[7]),\
"r"((r)[8]),"r"((r)[9]),"r"((r)[10]),"r"((r)[11]),"r"((r)[12]),"r"((r)[13]),"r"((r)[14]),"r"((r)[15]),\
"r"((r)[16]),"r"((r)[17]),"r"((r)[18]),"r"((r)[19]),"r"((r)[20]),"r"((r)[21]),"r"((r)[22]),"r"((r)[23]),\
"r"((r)[24]),"r"((r)[25]),"r"((r)[26]),"r"((r)[27]),"r"((r)[28]),"r"((r)[29]),"r"((r)[30]),"r"((r)[31])
#define W32(r) "=r"((r)[0]),"=r"((r)[1]),"=r"((r)[2]),"=r"((r)[3]),"=r"((r)[4]),"=r"((r)[5]),"=r"((r)[6]),"=r"((r)[7]),\
"=r"((r)[8]),"=r"((r)[9]),"=r"((r)[10]),"=r"((r)[11]),"=r"((r)[12]),"=r"((r)[13]),"=r"((r)[14]),"=r"((r)[15]),\
"=r"((r)[16]),"=r"((r)[17]),"=r"((r)[18]),"=r"((r)[19]),"=r"((r)[20]),"=r"((r)[21]),"=r"((r)[22]),"=r"((r)[23]),\
"=r"((r)[24]),"=r"((r)[25]),"=r"((r)[26]),"=r"((r)[27]),"=r"((r)[28]),"=r"((r)[29]),"=r"((r)[30]),"=r"((r)[31])

#define STTM32(a, r) asm volatile("tcgen05.st.sync.aligned.32x32b.x32.b32 [%0], {%1,%2,%3,%4,%5,%6,%7,%8,%9,%10,%11,%12,%13,%14,%15,%16,%17,%18,%19,%20,%21,%22,%23,%24,%25,%26,%27,%28,%29,%30,%31,%32};" :: "r"(a), R32(r) : "memory")
#define LDTM32(r, a) asm volatile("tcgen05.ld.sync.aligned.32x32b.x32.b32 {%0,%1,%2,%3,%4,%5,%6,%7,%8,%9,%10,%11,%12,%13,%14,%15,%16,%17,%18,%19,%20,%21,%22,%23,%24,%25,%26,%27,%28,%29,%30,%31}, [%32];" : W32(r) : "r"(a))

static __device__ __forceinline__ void a_row(const float* g, uint32_t thi, uint32_t tlo) {
    uint32_t whi[32], wlo[32];
    #pragma unroll
    for (int i = 0; i < 32; ++i) {
        float a = g[2 * i], b = g[2 * i + 1];
        __nv_bfloat16 ah = __float2bfloat16(a), bh = __float2bfloat16(b);
        __nv_bfloat16 al = __float2bfloat16(a - __bfloat162float(ah));
        __nv_bfloat16 bl = __float2bfloat16(b - __bfloat162float(bh));
        whi[i] = (uint32_t)__bfloat16_as_ushort(ah) | ((uint32_t)__bfloat16_as_ushort(bh) << 16);
        wlo[i] = (uint32_t)__bfloat16_as_ushort(al) | ((uint32_t)__bfloat16_as_ushort(bl) << 16);
    }
    STTM32(thi, whi); STTM32(tlo, wlo);
}

static __device__ __forceinline__ void mma_block(uint32_t tb, uint32_t dbase,
        uint32_t ahi, uint32_t alo, uint64_t dh, uint64_t dl) {
    #pragma unroll
    for (int tl = 0; tl < 2; ++tl) {
        uint32_t d = tb + dbase + tl * 32, ah = tb + ahi + tl * 32, al = tb + alo + tl * 32;
        #pragma unroll
        for (int kc = 0; kc < 4; ++kc) {
            mma_ts(d, ah + kc * 8, dh + kc * 2);
            mma_ts(d, al + kc * 8, dh + kc * 2);
            mma_ts(d, ah + kc * 8, dl + kc * 2);
        }
    }
}

static __device__ __forceinline__ void z_out(float* smf, uint32_t addr, int grow) {
    uint32_t zr[32];
    LDTM32(zr, addr);
    TC_WLD();
    float* zp = smf + FI_ZB + grow * 36;
    #pragma unroll
    for (int q = 0; q < 8; ++q)
        *(float4*)&zp[4 * q] = make_float4(__uint_as_float(zr[4 * q]),
            __uint_as_float(zr[4 * q + 1]), __uint_as_float(zr[4 * q + 2]),
            __uint_as_float(zr[4 * q + 3]));
}

static __device__ __forceinline__ void pw(float* smf, int hid, int bq, float* c,
                                          char* bhi, char* blo, float* hf) {
    const float* zb = smf + FI_ZB + bq * 8;
    float zi[8], zf[8], zg[8], zo[8];
    *(float4*)&zi[0] = *(const float4*)&zb[hid * 36];
    *(float4*)&zi[4] = *(const float4*)&zb[hid * 36 + 4];
    *(float4*)&zf[0] = *(const float4*)&zb[(64 + hid) * 36];
    *(float4*)&zf[4] = *(const float4*)&zb[(64 + hid) * 36 + 4];
    *(float4*)&zg[0] = *(const float4*)&zb[(128 + hid) * 36];
    *(float4*)&zg[4] = *(const float4*)&zb[(128 + hid) * 36 + 4];
    *(float4*)&zo[0] = *(const float4*)&zb[(192 + hid) * 36];
    *(float4*)&zo[4] = *(const float4*)&zb[(192 + hid) * 36 + 4];
    #pragma unroll
    for (int j = 0; j < 8; ++j) {
        float cc = sigf(zf[j]) * c[j] + sigf(zi[j]) * tanhf_(zg[j]);
        c[j] = cc;
        float h = sigf(zo[j]) * tanhf_(cc);
        int b = bq * 8 + j;
        __nv_bfloat16 hh = __float2bfloat16(h);
        __nv_bfloat16 hl = __float2bfloat16(h - __bfloat162float(hh));
        int off = b * 128 + hid * 2, sw = off ^ ((off >> 3) & 0x70);
        *(__nv_bfloat16*)(bhi + sw) = hh;
        *(__nv_bfloat16*)(blo + sw) = hl;
        if (hf) hf[b * 66 + hid] = h;
    }
}
#else
// ================= FMA fallback helpers =================
static __device__ __forceinline__ u64 splat2f(float v) {
    u64 r; unsigned u = __float_as_uint(v);
    asm("mov.b64 %0, {%1, %1};" : "=l"(r) : "r"(u));
    return r;
}
static __device__ __forceinline__ u64 pack2f(float a, float b) {
    u64 r; unsigned ua = __float_as_uint(a), ub = __float_as_uint(b);
    asm("mov.b64 %0, {%1, %2};" : "=l"(r) : "r"(ua), "r"(ub));
    return r;
}
static __device__ __forceinline__ void fma2(u64& d, u64 a, u64 b) {
    asm("fma.rn.f32x2 %0, %1, %2, %0;" : "+l"(d) : "l"(a), "l"(b));
}
static __device__ __forceinline__ float lo32(u64 v) { return __uint_as_float((unsigned)v); }
static __device__ __forceinline__ float hi32(u64 v) { return __uint_as_float((unsigned)(v >> 32)); }

// smem float offsets (fallback)
#define WT1_O 0
#define WT2_O (WT1_O + 64 * 256)
#define HA_O  (WT2_O + 128 * 256)
#define XT_O  (HA_O + 128 * 32)
#define B1_O  (XT_O + 64 * 34)
#define B2_O  (B1_O + 256)
#define WI1_O (B2_O + 256)
#define HW_O  (WI1_O + 256)

static __device__ __forceinline__ void pointwise_f(const u64 acc[4][4], float c[8], float* hdst) {
    float hv[8];
    #pragma unroll
    for (int p = 0; p < 4; ++p) {
        #pragma unroll
        for (int q = 0; q < 2; ++q) {
            int j = 2 * p + q;
            float zi = q ? hi32(acc[0][p]) : lo32(acc[0][p]);
            float zf = q ? hi32(acc[1][p]) : lo32(acc[1][p]);
            float zg = q ? hi32(acc[2][p]) : lo32(acc[2][p]);
            float zo = q ? hi32(acc[3][p]) : lo32(acc[3][p]);
            float cc = sigf(zf) * c[j] + sigf(zi) * tanhf_(zg);
            c[j] = cc;
            hv[j] = sigf(zo) * tanhf_(cc);
        }
    }
    *(float4*)&hdst[0] = make_float4(hv[0], hv[1], hv[2], hv[3]);
    *(float4*)&hdst[4] = make_float4(hv[4], hv[5], hv[6], hv[7]);
}

#define LOADK(K, b) { \
    int ha = HA_O + ((K) << 5) + (((bg + (K)) & 3) << 3); \
    ulonglong2 q0 = *(const ulonglong2*)&sm[ha]; \
    ulonglong2 q1 = *(const ulonglong2*)&sm[ha + 4]; \
    ulonglong2 q2 = *(const ulonglong2*)&sm[ha + 2048]; \
    ulonglong2 q3 = *(const ulonglong2*)&sm[ha + 2048 + 4]; \
    h1r[b][0] = q0.x; h1r[b][1] = q0.y; h1r[b][2] = q1.x; h1r[b][3] = q1.y; \
    h2r[b][0] = q2.x; h2r[b][1] = q2.y; h2r[b][2] = q3.x; h2r[b][3] = q3.y; \
    w1r[b]  = *(const float4*)&sm[WT1_O + (K) * 256 + hid4]; \
    w2ar[b] = *(const float4*)&sm[WT2_O + (K) * 256 + hid4]; \
    w2br[b] = *(const float4*)&sm[WT2_O + ((K) + 64) * 256 + hid4]; }

#define FMA_G(g, wv, accarr, hparr) { \
    u64 s = splat2f(wv); \
    fma2(accarr[g][0], s, hparr[0]); fma2(accarr[g][1], s, hparr[1]); \
    fma2(accarr[g][2], s, hparr[2]); fma2(accarr[g][3], s, hparr[3]); }

#define FMAK(b) { \
    FMA_G(0, w1r[b].x,  acc1, h1r[b]); FMA_G(1, w1r[b].y,  acc1, h1r[b]); \
    FMA_G(2, w1r[b].z,  acc1, h1r[b]); FMA_G(3, w1r[b].w,  acc1, h1r[b]); \
    FMA_G(0, w2ar[b].x, acc2, h1r[b]); FMA_G(1, w2ar[b].y, acc2, h1r[b]); \
    FMA_G(2, w2ar[b].z, acc2, h1r[b]); FMA_G(3, w2ar[b].w, acc2, h1r[b]); \
    FMA_G(0, w2br[b].x, acc2, h2r[b]); FMA_G(1, w2br[b].y, acc2, h2r[b]); \
    FMA_G(2, w2br[b].z, acc2, h2r[b]); FMA_G(3, w2br[b].w, acc2, h2r[b]); }
#endif

__global__ void __launch_bounds__(NT, 1)
lstm_kernel(const float* __restrict__ x,
            const float* __restrict__ W_ih1, const float* __restrict__ W_hh1,
            const float* __restrict__ b_ih1, const float* __restrict__ b_hh1,
            const float* __restrict__ W_ih2, const float* __restrict__ W_hh2,
            const float* __restrict__ b_ih2, const float* __restrict__ b_hh2,
            const float* __restrict__ W_d1, const float* __restrict__ b_d1,
            const float* __restrict__ W_d2, const float* __restrict__ b_d2,
            float* __restrict__ out)
{
#if TC_PATH
    char* smc = smraw;
    float* smf = (float*)smc;
    const int tid = threadIdx.x, lane = tid & 31, wrp = tid >> 5;
    const int wg = wrp >> 2, sub = wrp & 3;
    const int grow = wg * 128 + sub * 32 + lane;
    const int b0 = blockIdx.x * 32;
    const uint32_t sbase = smem_u32(smc);
    const uint32_t woff = (uint32_t)sub << 21;
    const uint32_t mb1 = sbase + SB_MBAR, mb2 = sbase + SB_MBAR + 8;

    if (wrp == 0) TC_ALLOC(sbase + SB_TMEMP, 512);
    __syncthreads();
    uint32_t tb;
    asm volatile("ld.shared.b32 %0, [%1];" : "=r"(tb) : "r"(sbase + SB_TMEMP));
    if (tid == 0) { MBAR_INIT(mb1, 1); MBAR_INIT(mb2, 1); }

    for (int i = tid; i < 256; i += NT) {
        smf[FI_WI1 + i] = W_ih1[i];
        smf[FI_B1 + i] = b_ih1[i] + b_hh1[i];
        smf[FI_B2 + i] = b_ih2[i] + b_hh2[i];
    }
    for (int i = tid; i < 8192; i += NT) ((uint32_t*)(smc + SB_T0))[i] = 0;

    a_row(W_hh1 + grow * 64, tb + 128 + wg * 32 + woff, tb + 192 + wg * 32 + woff);
    a_row(W_ih2 + grow * 64, tb + 256 + wg * 32 + woff, tb + 320 + wg * 32 + woff);
    a_row(W_hh2 + grow * 64, tb + 384 + wg * 32 + woff, tb + 448 + wg * 32 + woff);
    TC_WST();
    TC_FB();
    FENCE_ASYNC();
    __syncthreads();

    uint64_t dt[8];
    #pragma unroll
    for (int i = 0; i < 8; ++i) dt[i] = mkdesc(sbase + SB_T0 + i * 4096);

    float c1[8], c2[8];
    #pragma unroll
    for (int j = 0; j < 8; ++j) { c1[j] = 0.f; c2[j] = 0.f; }
    const int hid = tid & 63, bq = tid >> 6;
    const float wi = smf[FI_WI1 + grow], bb1 = smf[FI_B1 + grow], bb2 = smf[FI_B2 + grow];

    for (int t = 0; t < SEQ; ++t) {
        if ((t & 15) == 0) {
            for (int i = tid; i < 512; i += NT) {
                int row = i >> 4, tq = i & 15;
                smf[FI_XT + tq * 36 + row] = x[(size_t)(b0 + row) * SEQ + t + tq];
            }
            __syncthreads();
        }
        const int tt = t & 15, ph = t & 1;
        const int h1c = ph ? 2 : 0, h1p = ph ? 0 : 2;
        const int h2c = ph ? 6 : 4, h2p = ph ? 4 : 6;

        // A: D init (fp32 exact bias + x*w_ih1)
        {
            uint32_t r1[32], r2[32];
            #pragma unroll
            for (int q = 0; q < 8; ++q) {
                float4 xv = *(const float4*)&smf[FI_XT + tt * 36 + 4 * q];
                r1[4 * q + 0] = __float_as_uint(fmaf(xv.x, wi, bb1));
                r1[4 * q + 1] = __float_as_uint(fmaf(xv.y, wi, bb1));
                r1[4 * q + 2] = __float_as_uint(fmaf(xv.z, wi, bb1));
                r1[4 * q + 3] = __float_as_uint(fmaf(xv.w, wi, bb1));
            }
            #pragma unroll
            for (int q = 0; q < 32; ++q) r2[q] = __float_as_uint(bb2);
            STTM32(tb + 0 + wg * 32 + woff, r1);
            STTM32(tb + 64 + wg * 32 + woff, r2);
            TC_WST();
        }
        TC_FB();
        __syncthreads();

        // B: L1 MMAs (commit mb1) + L2*h2prev MMAs (queued)
        if (wrp == 0) {
            TC_FA();
            if (elect1()) {
                mma_block(tb, 0, 128, 192, dt[h1p], dt[h1p + 1]);
                TC_COMMIT(mb1);
                mma_block(tb, 64, 384, 448, dt[h2p], dt[h2p + 1]);
            }
        }

        // C: z1
        MBAR_WAIT(mb1, ph);
        TC_FA();
        z_out(smf, tb + wg * 32, grow);
        __syncthreads();

        // D: PW1 -> h1 cur
        pw(smf, hid, bq, c1, smc + SB_T0 + h1c * 4096, smc + SB_T0 + (h1c + 1) * 4096, nullptr);
        FENCE_ASYNC();
        __syncthreads();

        // E: L2*h1cur MMAs (commit mb2)
        if (wrp == 0) {
            TC_FA();
            if (elect1()) {
                mma_block(tb, 64, 256, 320, dt[h1c], dt[h1c + 1]);
                TC_COMMIT(mb2);
            }
        }

        // F: z2
        MBAR_WAIT(mb2, ph);
        TC_FA();
        z_out(smf, tb + 64 + wg * 32, grow);
        __syncthreads();

        // G: PW2 -> h2 cur
        pw(smf, hid, bq, c2, smc + SB_T0 + h2c * 4096, smc + SB_T0 + (h2c + 1) * 4096,
           (t == SEQ - 1) ? &smf[FI_H2F] : nullptr);
        FENCE_ASYNC();
        __syncthreads();
    }

    if (wrp == 0) { TC_RELINQ(); TC_DEALLOC(tb, 512); }

    // dense head on fp32 h2[511]
    for (int i = tid; i < 2048; i += NT) smf[FI_ZB + i] = W_d1[i];
    for (int i = tid; i < 768; i += NT) smf[FI_ZB + 2048 + i] = W_d2[i];
    if (tid < 32) smf[FI_ZB + 2816 + tid] = b_d1[tid];
    if (tid < 24) smf[FI_ZB + 2848 + tid] = b_d2[tid];
    __syncthreads();

    for (int idx = tid; idx < 1024; idx += NT) {
        int b = idx >> 5, j = idx & 31;
        float a = smf[FI_ZB + 2816 + j];
        #pragma unroll 8
        for (int k = 0; k < 64; ++k)
            a += smf[FI_H2F + b * 66 + k] * smf[FI_ZB + j * 64 + k];
        smf[FI_ZB + 2880 + b * 32 + j] = fmaxf(a, 0.f);
    }
    __syncthreads();
    for (int idx = tid; idx < 768; idx += NT) {
        int b = idx / 24, o = idx - b * 24;
        float a = smf[FI_ZB + 2848 + o];
        #pragma unroll 8
        for (int j = 0; j < 32; ++j)
            a += smf[FI_ZB + 2880 + b * 32 + j] * smf[FI_ZB + 2048 + o * 32 + j];
        out[(size_t)(b0 + b) * 24 + o] = a;
    }
#else
    // ================= FMA fallback (R4, 4786us) =================
    float* sm = (float*)smraw;
    const int tid  = threadIdx.x;
    const int lane = tid & 31;
    const int wrp  = tid >> 5;
    const int hid  = ((wrp & 1) << 5) | lane;
    const int bg   = wrp >> 1;
    const int b0   = blockIdx.x * 32;
    const int octh = ((bg + hid) & 3) << 3;
    const int hid4 = hid << 2;

    for (int i = tid; i < 64 * 256; i += NT) {
        int k = i >> 8, r = i & 255;
        int g = r >> 6, h = r & 63;
        sm[WT1_O + k * 256 + h * 4 + g] = W_hh1[r * 64 + k];
    }
    for (int i = tid; i < 64 * 256; i += NT) {
        int k = i >> 8, r = i & 255;
        int g = r >> 6, h = r & 63;
        sm[WT2_O + k * 256 + h * 4 + g] = W_ih2[r * 64 + k];
    }
    for (int i = tid; i < 64 * 256; i += NT) {
        int k = i >> 8, r = i & 255;
        int g = r >> 6, h = r & 63;
        sm[WT2_O + (64 + k) * 256 + h * 4 + g] = W_hh2[r * 64 + k];
    }
    for (int i = tid; i < 256; i += NT) {
        sm[B1_O + i]  = b_ih1[i] + b_hh1[i];
        sm[B2_O + i]  = b_ih2[i] + b_hh2[i];
        sm[WI1_O + i] = W_ih1[i];
    }
    for (int i = tid; i < 128 * 32; i += NT) sm[HA_O + i] = 0.f;
    {
        #pragma unroll
        for (int it = 0; it < 2; ++it) {
            int i = tid + it * NT;
            int row = i >> 4, q = (i & 15) << 2;
            float4 v = *(const float4*)(x + (size_t)(b0 + row) * SEQ + q);
            sm[XT_O + (q + 0) * 34 + row] = v.x;
            sm[XT_O + (q + 1) * 34 + row] = v.y;
            sm[XT_O + (q + 2) * 34 + row] = v.z;
            sm[XT_O + (q + 3) * 34 + row] = v.w;
        }
    }
    __syncthreads();

    u64   acc1[4][4], acc2[4][4];
    float c1[8], c2[8];
    #pragma unroll
    for (int j = 0; j < 8; ++j) { c1[j] = 0.f; c2[j] = 0.f; }

    float* h1dst = &sm[HA_O + hid * 32 + octh];
    float* h2dst = &sm[HA_O + (64 + hid) * 32 + octh];

    {
        u64 xp[4];
        #pragma unroll
        for (int p = 0; p < 4; ++p)
            xp[p] = *(const u64*)&sm[XT_O + 0 * 34 + bg * 8 + 2 * p];
        #pragma unroll
        for (int g = 0; g < 4; ++g) {
            u64 sb = splat2f(sm[B1_O + g * 64 + hid]);
            u64 sw = splat2f(sm[WI1_O + g * 64 + hid]);
            #pragma unroll
            for (int p = 0; p < 4; ++p) { acc1[g][p] = sb; fma2(acc1[g][p], sw, xp[p]); }
        }
        pointwise_f(acc1, c1, h1dst);
    }
    __syncthreads();

    for (int t = 0; t < SEQ; ++t) {
        if (((t + 1) & 63) == 0 && (t + 1) < SEQ) {
            int base = t + 1;
            #pragma unroll
            for (int it = 0; it < 2; ++it) {
                int i = tid + it * NT;
                int row = i >> 4, q = (i & 15) << 2;
                float4 v = *(const float4*)(x + (size_t)(b0 + row) * SEQ + base + q);
                sm[XT_O + (q + 0) * 34 + row] = v.x;
                sm[XT_O + (q + 1) * 34 + row] = v.y;
                sm[XT_O + (q + 2) * 34 + row] = v.z;
                sm[XT_O + (q + 3) * 34 + row] = v.w;
            }
            __syncthreads();
        }
        const int tt = ((t + 1) < SEQ ? (t + 1) : t) & 63;

        #pragma unroll
        for (int g = 0; g < 4; ++g) {
            u64 s = splat2f(sm[B2_O + g * 64 + hid]);
            #pragma unroll
            for (int p = 0; p < 4; ++p) acc2[g][p] = s;
        }
        {
            u64 xp[4];
            #pragma unroll
            for (int p = 0; p < 4; ++p)
                xp[p] = *(const u64*)&sm[XT_O + tt * 34 + bg * 8 + 2 * p];
            #pragma unroll
            for (int g = 0; g < 4; ++g) {
                u64 sb = splat2f(sm[B1_O + g * 64 + hid]);
                u64 sw = splat2f(sm[WI1_O + g * 64 + hid]);
                #pragma unroll
                for (int p = 0; p < 4; ++p) { acc1[g][p] = sb; fma2(acc1[g][p], sw, xp[p]); }
            }
        }

        {
            u64 h1r[2][4], h2r[2][4];
            float4 w1r[2], w2ar[2], w2br[2];
            LOADK(0, 0);
            #pragma unroll 2
            for (int k = 0; k < 64; ++k) {
                const int cur = k & 1;
                if (k < 63) LOADK(k + 1, cur ^ 1);
                FMAK(cur);
            }
        }
        __syncthreads();

        pointwise_f(acc2, c2, h2dst);
        if (t + 1 < SEQ) pointwise_f(acc1, c1, h1dst);
        __syncthreads();
    }

    for (int i = tid; i < 32 * 64; i += NT) sm[XT_O + i] = W_d1[i];
    for (int i = tid; i < 24 * 32; i += NT) sm[HW_O + i] = W_d2[i];
    if (tid < 32) sm[HW_O + 768 + tid] = b_d1[tid];
    if (tid < 24) sm[HW_O + 800 + tid] = b_d2[tid];
    __syncthreads();

    for (int idx = tid; idx < 32 * 32; idx += NT) {
        int b = idx >> 5, j = idx & 31;
        int ob = b >> 3, bl = b & 7;
        float a = sm[HW_O + 768 + j];
        #pragma unroll 8
        for (int k = 0; k < 64; ++k) {
            float hv = sm[HA_O + (64 + k) * 32 + (((ob + k) & 3) << 3) + bl];
            a += hv * sm[XT_O + j * 64 + k];
        }
        sm[HA_O + b * 32 + j] = fmaxf(a, 0.f);
    }
    __syncthreads();
    for (int idx = tid; idx < 32 * 24; idx += NT) {
        int b = idx / 24, o = idx - b * 24;
        float a = sm[HW_O + 800 + o];
        #pragma unroll 8
        for (int j = 0; j < 32; ++j)
            a += sm[HA_O + b * 32 + j] * sm[HW_O + o * 32 + j];
        out[(size_t)(b0 + b) * 24 + o] = a;
    }
#endif
}

extern "C" void kernel_launch(void* const* d_in, const int* in_sizes, int n_in,
                              void* d_out, int out_size)
{
    const float* x     = (const float*)d_in[0];
    const float* W_ih1 = (const float*)d_in[1];
    const float* W_hh1 = (const float*)d_in[2];
    const float* b_ih1 = (const float*)d_in[3];
    const float* b_hh1 = (const float*)d_in[4];
    const float* W_ih2 = (const float*)d_in[5];
    const float* W_hh2 = (const float*)d_in[6];
    const float* b_ih2 = (const float*)d_in[7];
    const float* b_hh2 = (const float*)d_in[8];
    const float* W_d1  = (const float*)d_in[9];
    const float* b_d1  = (const float*)d_in[10];
    const float* W_d2  = (const float*)d_in[11];
    const float* b_d2  = (const float*)d_in[12];
    float* out = (float*)d_out;

    cudaFuncSetAttribute(lstm_kernel,
                         cudaFuncAttributeMaxDynamicSharedMemorySize, SM_BYTES_HOST);
    lstm_kernel<<<NBLK, NT, SM_BYTES_HOST>>>(
        x, W_ih1, W_hh1, b_ih1, b_hh1, W_ih2, W_hh2, b_ih2, b_hh2,
        W_d1, b_d1, W_d2, b_d2, out);
}

// round 15
// speedup vs baseline: 1.0121x; 1.0109x over previous
#include <cuda_runtime.h>
#include <cuda_bf16.h>
#include <cstdint>

#define NT   256
#define NBLK 128
#define SEQ  512

#if defined(__CUDA_ARCH_FEAT_SM103_ALL)
#define TC_PATH 1
#else
#define TC_PATH 0
#endif

#define SM_BYTES_HOST 228096

typedef unsigned long long u64;

static __device__ __forceinline__ float sigf(float x) {
    return __fdividef(1.f, 1.f + __expf(-x));
}
static __device__ __forceinline__ float tanhf_(float x) {
    float xx = fmaxf(x, -30.f);
    float e  = __expf(-2.f * xx);
    return __fdividef(1.f - e, 1.f + e);
}

extern __shared__ char smraw[];

#if TC_PATH
// ================= tcgen05 path =================
#define IDESC 0x8080490u  // f16 MMA: F32 acc, bf16 a/b, M=128, N=32

#define SB_MBAR  0
#define SB_TMEMP 16
#define FI_WI1 8
#define FI_B1  264
#define FI_B2  520
#define FI_XT  776            // 16 x 36
#define FI_H2F 1352           // 32 x 66
#define FI_AB  3464           // 256 x 36 activated-exchange buffer
#define SB_T0  51200          // 8 bf16 tiles x 4KB (SW128 32x128B)
// tiles: 0 H1A_hi 1 H1A_lo 2 H1B_hi 3 H1B_lo 4 H2A_hi 5 H2A_lo 6 H2B_hi 7 H2B_lo

static __device__ __forceinline__ uint32_t smem_u32(const void* p) {
    uint32_t a;
    asm("{ .reg .u64 t; cvta.to.shared.u64 t, %1; cvt.u32.u64 %0, t; }" : "=r"(a) : "l"(p));
    return a;
}
static __device__ __forceinline__ uint32_t elect1() {
    uint32_t p;
    asm volatile("{ .reg .pred p; elect.sync _|p, 0xFFFFFFFF; selp.b32 %0,1,0,p; }" : "=r"(p));
    return p;
}
static __device__ __forceinline__ uint64_t mkdesc(uint32_t sa) {
    const uint64_t base = (2ULL << 61) | (1ULL << 46) | (64ULL << 32) | (1ULL << 16);
    return base | ((uint64_t)(sa >> 4) & 0x3FFF);
}
static __device__ __forceinline__ void mma_ts(uint32_t d, uint32_t a, uint64_t bd) {
    asm volatile("{ .reg .pred p; setp.eq.u32 p,1,1;\n\t"
        "tcgen05.mma.cta_group::1.kind::f16 [%0], [%1], %2, %3, {%4,%4,%4,%4}, p; }"
        :: "r"(d), "r"(a), "l"(bd), "r"(IDESC), "r"(0u) : "memory");
}
static __device__ __forceinline__ void mma_ts0(uint32_t d, uint32_t a, uint64_t bd) {
    asm volatile("{ .reg .pred p; setp.eq.u32 p,1,0;\n\t"
        "tcgen05.mma.cta_group::1.kind::f16 [%0], [%1], %2, %3, {%4,%4,%4,%4}, p; }"
        :: "r"(d), "r"(a), "l"(bd), "r"(IDESC), "r"(0u) : "memory");
}
#define TC_ALLOC(sa,n)  asm volatile("tcgen05.alloc.cta_group::1.sync.aligned.shared::cta.b32 [%0], %1;" :: "r"(sa), "r"(n) : "memory")
#define TC_DEALLOC(t,n) asm volatile("tcgen05.dealloc.cta_group::1.sync.aligned.b32 %0, %1;" :: "r"(t), "r"(n))
#define TC_RELINQ()     asm volatile("tcgen05.relinquish_alloc_permit.cta_group::1.sync.aligned;")
#define TC_WST()        asm volatile("tcgen05.wait::st.sync.aligned;" ::: "memory")
#define TC_WLD()        asm volatile("tcgen05.wait::ld.sync.aligned;" ::: "memory")
#define TC_FB()         asm volatile("tcgen05.fence::before_thread_sync;" ::: "memory")
#define TC_FA()         asm volatile("tcgen05.fence::after_thread_sync;" ::: "memory")
#define TC_COMMIT(mb)   asm volatile("tcgen05.commit.cta_group::1.mbarrier::arrive::one.shared::cluster.b64 [%0];" :: "r"(mb) : "memory")
#define FENCE_ASYNC()   asm volatile("fence.proxy.async.shared::cta;" ::: "memory")
#define MBAR_INIT(mb,n) asm volatile("mbarrier.init.shared.b64 [%0], %1;" :: "r"(mb), "r"(n) : "memory")
#define MBAR_WAIT(mb,par) do { uint32_t _m=(mb),_p=(par),_d; \
    asm volatile("{ .reg .pred p; mbarrier.try_wait.parity.acquire.cta.shared::cta.b64 p, [%1], %2; selp.b32 %0,1,0,p; }" : "=r"(_d) : "r"(_m), "r"(_p) : "memory"); \
    if (!_d) asm volatile("{ .reg .pred P1; WL%=: mbarrier.try_wait.parity.acquire.cta.shared::cta.b64 P1, [%0], %1, 0x989680; @P1 bra.uni WD%=; bra.uni WL%=; WD%=: }" :: "r"(_m), "r"(_p) : "memory"); \
    } while (0)

#define R32(r) "r"((r)[0]),"r"((r)[1]),"r"((r)[2]),"r"((r)[3]),"r"((r)[4]),"r"((r)[5]),"r"((r)[6]),"r"((r)[7]),\
"r"((r)[8]),"r"((r)[9]),"r"((r)[10]),"r"((r)[11]),"r"((r)[12]),"r"((r)[13]),"r"((r)[14]),"r"((r)[15]),\
"r"((r)[16]),"r"((r)[17]),"r"((r)[18]),"r"((r)[19]),"r"((r)[20]),"r"((r)[21]),"r"((r)[22]),"r"((r)[23]),\
"r"((r)[24]),"r"((r)[25]),"r"((r)[26]),"r"((r)[27]),"r"((r)[28]),"r"((r)[29]),"r"((r)[30]),"r"((r)[31])
#define W32(r) "=r"((r)[0]),"=r"((r)[1]),"=r"((r)[2]),"=r"((r)[3]),"=r"((r)[4]),"=r"((r)[5]),"=r"((r)[6]),"=r"((r)[7]),\
"=r"((r)[8]),"=r"((r)[9]),"=r"((r)[10]),"=r"((r)[11]),"=r"((r)[12]),"=r"((r)[13]),"=r"((r)[14]),"=r"((r)[15]),\
"=r"((r)[16]),"=r"((r)[17]),"=r"((r)[18]),"=r"((r)[19]),"=r"((r)[20]),"=r"((r)[21]),"=r"((r)[22]),"=r"((r)[23]),\
"=r"((r)[24]),"=r"((r)[25]),"=r"((r)[26]),"=r"((r)[27]),"=r"((r)[28]),"=r"((r)[29]),"=r"((r)[30]),"=r"((r)[31])

#define STTM32(a, r) asm volatile("tcgen05.st.sync.aligned.32x32b.x32.b32 [%0], {%1,%2,%3,%4,%5,%6,%7,%8,%9,%10,%11,%12,%13,%14,%15,%16,%17,%18,%19,%20,%21,%22,%23,%24,%25,%26,%27,%28,%29,%30,%31,%32};" :: "r"(a), R32(r) : "memory")
#define LDTM32(r, a) asm volatile("tcgen05.ld.sync.aligned.32x32b.x32.b32 {%0,%1,%2,%3,%4,%5,%6,%7,%8,%9,%10,%11,%12,%13,%14,%15,%16,%17,%18,%19,%20,%21,%22,%23,%24,%25,%26,%27,%28,%29,%30,%31}, [%32];" : W32(r) : "r"(a))

static __device__ __forceinline__ void a_row(const float* g, uint32_t thi, uint32_t tlo) {
    uint32_t whi[32], wlo[32];
    #pragma unroll
    for (int i = 0; i < 32; ++i) {
        float a = g[2 * i], b = g[2 * i + 1];
        __nv_bfloat16 ah = __float2bfloat16(a), bh = __float2bfloat16(b);
        __nv_bfloat16 al = __float2bfloat16(a - __bfloat162float(ah));
        __nv_bfloat16 bl = __float2bfloat16(b - __bfloat162float(bh));
        whi[i] = (uint32_t)__bfloat16_as_ushort(ah) | ((uint32_t)__bfloat16_as_ushort(bh) << 16);
        wlo[i] = (uint32_t)__bfloat16_as_ushort(al) | ((uint32_t)__bfloat16_as_ushort(bl) << 16);
    }
    STTM32(thi, whi); STTM32(tlo, wlo);
}

// 24 MMAs: D(dbase) (+)= A(hi/lo) x B(hi/lo), 2 tiles x 4 kc x 3 passes.
// init: first MMA per D tile overwrites (enable_d = 0).
static __device__ __forceinline__ void mma_blk(uint32_t tb, uint32_t dbase,
        uint32_t ahi, uint32_t alo, uint64_t dh, uint64_t dl, bool init) {
    #pragma unroll
    for (int tl = 0; tl < 2; ++tl) {
        uint32_t d = tb + dbase + tl * 32, ah = tb + ahi + tl * 32, al = tb + alo + tl * 32;
        #pragma unroll
        for (int kc = 0; kc < 4; ++kc) {
            if (kc == 0 && init) mma_ts0(d, ah, dh);
            else                 mma_ts(d, ah + kc * 8, dh + kc * 2);
            mma_ts(d, al + kc * 8, dh + kc * 2);
            mma_ts(d, ah + kc * 8, dl + kc * 2);
        }
    }
}

// LDTM one D half, fold bias (+ optional x*w), activate (gate-uniform per warp),
// scatter activated values to AB exchange buffer.
static __device__ __forceinline__ void act(float* smf, uint32_t tmaddr, int grow,
                                           float bb, float wi, const float* xrow) {
    uint32_t zr[32];
    LDTM32(zr, tmaddr);
    TC_WLD();
    float* zp = smf + FI_AB + grow * 36;
    const int gate = grow >> 6;
    if (gate == 2) {
        #pragma unroll
        for (int q = 0; q < 8; ++q) {
            float4 xv = xrow ? *(const float4*)&xrow[4 * q] : make_float4(0.f, 0.f, 0.f, 0.f);
            float4 o;
            o.x = tanhf_(__uint_as_float(zr[4 * q + 0]) + fmaf(wi, xv.x, bb));
            o.y = tanhf_(__uint_as_float(zr[4 * q + 1]) + fmaf(wi, xv.y, bb));
            o.z = tanhf_(__uint_as_float(zr[4 * q + 2]) + fmaf(wi, xv.z, bb));
            o.w = tanhf_(__uint_as_float(zr[4 * q + 3]) + fmaf(wi, xv.w, bb));
            *(float4*)&zp[4 * q] = o;
        }
    } else {
        #pragma unroll
        for (int q = 0; q < 8; ++q) {
            float4 xv = xrow ? *(const float4*)&xrow[4 * q] : make_float4(0.f, 0.f, 0.f, 0.f);
            float4 o;
            o.x = sigf(__uint_as_float(zr[4 * q + 0]) + fmaf(wi, xv.x, bb));
            o.y = sigf(__uint_as_float(zr[4 * q + 1]) + fmaf(wi, xv.y, bb));
            o.z = sigf(__uint_as_float(zr[4 * q + 2]) + fmaf(wi, xv.z, bb));
            o.w = sigf(__uint_as_float(zr[4 * q + 3]) + fmaf(wi, xv.w, bb));
            *(float4*)&zp[4 * q] = o;
        }
    }
}

// cell update from activated gates; write h bf16 hi/lo into SW128 tiles.
static __device__ __forceinline__ void upd(float* smf, int hid, int bq, float* c,
                                           char* bhi, char* blo, float* hf) {
    const float* ab = smf + FI_AB + bq * 8;
    float ai[8], af[8], ag[8], ao[8];
    *(float4*)&ai[0] = *(const float4*)&ab[hid * 36];
    *(float4*)&ai[4] = *(const float4*)&ab[hid * 36 + 4];
    *(float4*)&af[0] = *(const float4*)&ab[(64 + hid) * 36];
    *(float4*)&af[4] = *(const float4*)&ab[(64 + hid) * 36 + 4];
    *(float4*)&ag[0] = *(const float4*)&ab[(128 + hid) * 36];
    *(float4*)&ag[4] = *(const float4*)&ab[(128 + hid) * 36 + 4];
    *(float4*)&ao[0] = *(const float4*)&ab[(192 + hid) * 36];
    *(float4*)&ao[4] = *(const float4*)&ab[(192 + hid) * 36 + 4];
    #pragma unroll
    for (int j = 0; j < 8; ++j) {
        float cc = fmaf(af[j], c[j], ai[j] * ag[j]);
        c[j] = cc;
        float h = ao[j] * tanhf_(cc);
        int b = bq * 8 + j;
        __nv_bfloat16 hh = __float2bfloat16(h);
        __nv_bfloat16 hl = __float2bfloat16(h - __bfloat162float(hh));
        int off = b * 128 + hid * 2, sw = off ^ ((off >> 3) & 0x70);
        *(__nv_bfloat16*)(bhi + sw) = hh;
        *(__nv_bfloat16*)(blo + sw) = hl;
        if (hf) hf[b * 66 + hid] = h;
    }
}
#else
// ================= FMA fallback helpers (R4) =================
static __device__ __forceinline__ u64 splat2f(float v) {
    u64 r; unsigned u = __float_as_uint(v);
    asm("mov.b64 %0, {%1, %1};" : "=l"(r) : "r"(u));
    return r;
}
static __device__ __forceinline__ void fma2(u64& d, u64 a, u64 b) {
    asm("fma.rn.f32x2 %0, %1, %2, %0;" : "+l"(d) : "l"(a), "l"(b));
}
static __device__ __forceinline__ float lo32(u64 v) { return __uint_as_float((unsigned)v); }
static __device__ __forceinline__ float hi32(u64 v) { return __uint_as_float((unsigned)(v >> 32)); }

#define WT1_O 0
#define WT2_O (WT1_O + 64 * 256)
#define HA_O  (WT2_O + 128 * 256)
#define XT_O  (HA_O + 128 * 32)
#define B1_O  (XT_O + 64 * 34)
#define B2_O  (B1_O + 256)
#define WI1_O (B2_O + 256)
#define HW_O  (WI1_O + 256)

static __device__ __forceinline__ void pointwise_f(const u64 acc[4][4], float c[8], float* hdst) {
    float hv[8];
    #pragma unroll
    for (int p = 0; p < 4; ++p) {
        #pragma unroll
        for (int q = 0; q < 2; ++q) {
            int j = 2 * p + q;
            float zi = q ? hi32(acc[0][p]) : lo32(acc[0][p]);
            float zf = q ? hi32(acc[1][p]) : lo32(acc[1][p]);
            float zg = q ? hi32(acc[2][p]) : lo32(acc[2][p]);
            float zo = q ? hi32(acc[3][p]) : lo32(acc[3][p]);
            float cc = sigf(zf) * c[j] + sigf(zi) * tanhf_(zg);
            c[j] = cc;
            hv[j] = sigf(zo) * tanhf_(cc);
        }
    }
    *(float4*)&hdst[0] = make_float4(hv[0], hv[1], hv[2], hv[3]);
    *(float4*)&hdst[4] = make_float4(hv[4], hv[5], hv[6], hv[7]);
}

#define LOADK(K, b) { \
    int ha = HA_O + ((K) << 5) + (((bg + (K)) & 3) << 3); \
    ulonglong2 q0 = *(const ulonglong2*)&sm[ha]; \
    ulonglong2 q1 = *(const ulonglong2*)&sm[ha + 4]; \
    ulonglong2 q2 = *(const ulonglong2*)&sm[ha + 2048]; \
    ulonglong2 q3 = *(const ulonglong2*)&sm[ha + 2048 + 4]; \
    h1r[b][0] = q0.x; h1r[b][1] = q0.y; h1r[b][2] = q1.x; h1r[b][3] = q1.y; \
    h2r[b][0] = q2.x; h2r[b][1] = q2.y; h2r[b][2] = q3.x; h2r[b][3] = q3.y; \
    w1r[b]  = *(const float4*)&sm[WT1_O + (K) * 256 + hid4]; \
    w2ar[b] = *(const float4*)&sm[WT2_O + (K) * 256 + hid4]; \
    w2br[b] = *(const float4*)&sm[WT2_O + ((K) + 64) * 256 + hid4]; }

#define FMA_G(g, wv, accarr, hparr) { \
    u64 s = splat2f(wv); \
    fma2(accarr[g][0], s, hparr[0]); fma2(accarr[g][1], s, hparr[1]); \
    fma2(accarr[g][2], s, hparr[2]); fma2(accarr[g][3], s, hparr[3]); }

#define FMAK(b) { \
    FMA_G(0, w1r[b].x,  acc1, h1r[b]); FMA_G(1, w1r[b].y,  acc1, h1r[b]); \
    FMA_G(2, w1r[b].z,  acc1, h1r[b]); FMA_G(3, w1r[b].w,  acc1, h1r[b]); \
    FMA_G(0, w2ar[b].x, acc2, h1r[b]); FMA_G(1, w2ar[b].y, acc2, h1r[b]); \
    FMA_G(2, w2ar[b].z, acc2, h1r[b]); FMA_G(3, w2ar[b].w, acc2, h1r[b]); \
    FMA_G(0, w2br[b].x, acc2, h2r[b]); FMA_G(1, w2br[b].y, acc2, h2r[b]); \
    FMA_G(2, w2br[b].z, acc2, h2r[b]); FMA_G(3, w2br[b].w, acc2, h2r[b]); }
#endif

__global__ void __launch_bounds__(NT, 1)
lstm_kernel(const float* __restrict__ x,
            const float* __restrict__ W_ih1, const float* __restrict__ W_hh1,
            const float* __restrict__ b_ih1, const float* __restrict__ b_hh1,
            const float* __restrict__ W_ih2, const float* __restrict__ W_hh2,
            const float* __restrict__ b_ih2, const float* __restrict__ b_hh2,
            const float* __restrict__ W_d1, const float* __restrict__ b_d1,
            const float* __restrict__ W_d2, const float* __restrict__ b_d2,
            float* __restrict__ out)
{
#if TC_PATH
    char* smc = smraw;
    float* smf = (float*)smc;
    const int tid = threadIdx.x, lane = tid & 31, wrp = tid >> 5;
    const int wg = wrp >> 2, sub = wrp & 3;
    const int grow = wg * 128 + sub * 32 + lane;
    const int b0 = blockIdx.x * 32;
    const uint32_t sbase = smem_u32(smc);
    const uint32_t woff = (uint32_t)sub << 21;
    const uint32_t mb1 = sbase + SB_MBAR, mb2 = sbase + SB_MBAR + 8;

    if (wrp == 0) TC_ALLOC(sbase + SB_TMEMP, 512);
    __syncthreads();
    uint32_t tb;
    asm volatile("ld.shared.b32 %0, [%1];" : "=r"(tb) : "r"(sbase + SB_TMEMP));
    if (tid == 0) { MBAR_INIT(mb1, 1); MBAR_INIT(mb2, 1); }

    for (int i = tid; i < 256; i += NT) {
        smf[FI_WI1 + i] = W_ih1[i];
        smf[FI_B1 + i] = b_ih1[i] + b_hh1[i];
        smf[FI_B2 + i] = b_ih2[i] + b_hh2[i];
    }
    for (int i = tid; i < 8192; i += NT) ((uint32_t*)(smc + SB_T0))[i] = 0;

    a_row(W_hh1 + grow * 64, tb + 128 + wg * 32 + woff, tb + 192 + wg * 32 + woff);
    a_row(W_ih2 + grow * 64, tb + 256 + wg * 32 + woff, tb + 320 + wg * 32 + woff);
    a_row(W_hh2 + grow * 64, tb + 384 + wg * 32 + woff, tb + 448 + wg * 32 + woff);
    TC_WST();
    TC_FB();
    FENCE_ASYNC();
    __syncthreads();

    uint64_t dt[8];
    #pragma unroll
    for (int i = 0; i < 8; ++i) dt[i] = mkdesc(sbase + SB_T0 + i * 4096);

    float c1[8], c2[8];
    #pragma unroll
    for (int j = 0; j < 8; ++j) { c1[j] = 0.f; c2[j] = 0.f; }
    const int hid = tid & 63, bq = tid >> 6;
    const float wi = smf[FI_WI1 + grow], bb1 = smf[FI_B1 + grow], bb2 = smf[FI_B2 + grow];

    // prologue: D1 = W_hh1 * 0 (enable0 over zeroed tile), commit mb1;
    //           D2 = W_hh2 * 0 (enable0), no commit (mb2 comes with L2ih(0)).
    if (wrp == 0) {
        TC_FA();
        if (elect1()) {
            mma_blk(tb, 0, 128, 192, dt[2], dt[3], true);
            TC_COMMIT(mb1);
            mma_blk(tb, 64, 384, 448, dt[6], dt[7], true);
        }
    }

    for (int t = 0; t < SEQ; ++t) {
        if ((t & 15) == 0) {
            for (int i = tid; i < 512; i += NT) {
                int row = i >> 4, tq = i & 15;
                smf[FI_XT + tq * 36 + row] = x[(size_t)(b0 + row) * SEQ + t + tq];
            }
            __syncthreads();
        }
        const int tt = t & 15, ph = t & 1;
        const int h1c = ph ? 2 : 0;   // h1 tile written this step
        const int h2c = ph ? 6 : 4;   // h2 tile written this step

        // P1: z1 -> activated gates
        MBAR_WAIT(mb1, ph);
        TC_FA();
        act(smf, tb + wg * 32, grow, bb1, wi, &smf[FI_XT + tt * 36]);
        __syncthreads();

        // P2: update h1
        upd(smf, hid, bq, c1, smc + SB_T0 + h1c * 4096, smc + SB_T0 + (h1c + 1) * 4096, nullptr);
        FENCE_ASYNC();
        __syncthreads();

        // I1: L2ih(t)*h1(t) -> D2 (accumulate), commit mb2;
        //     L1(t+1)*h1(t) -> D1 (enable0 overwrite), commit mb1.
        if (wrp == 0) {
            TC_FA();
            if (elect1()) {
                mma_blk(tb, 64, 256, 320, dt[h1c], dt[h1c + 1], false);
                TC_COMMIT(mb2);
                if (t + 1 < SEQ) {
                    mma_blk(tb, 0, 128, 192, dt[h1c], dt[h1c + 1], true);
                    TC_COMMIT(mb1);
                }
            }
        }

        // P4: z2 -> activated gates
        MBAR_WAIT(mb2, ph);
        TC_FA();
        act(smf, tb + 64 + wg * 32, grow, bb2, 0.f, nullptr);
        __syncthreads();

        // P5: update h2
        upd(smf, hid, bq, c2, smc + SB_T0 + h2c * 4096, smc + SB_T0 + (h2c + 1) * 4096,
            (t == SEQ - 1) ? &smf[FI_H2F] : nullptr);
        FENCE_ASYNC();
        __syncthreads();

        // I2: L2hh(t)*h2(t) -> D2 (enable0 overwrite), no commit yet.
        if (t + 1 < SEQ && wrp == 0) {
            TC_FA();
            if (elect1())
                mma_blk(tb, 64, 384, 448, dt[h2c], dt[h2c + 1], true);
        }
    }

    if (wrp == 0) { TC_RELINQ(); TC_DEALLOC(tb, 512); }

    // dense head on fp32 h2[511]
    for (int i = tid; i < 2048; i += NT) smf[FI_AB + i] = W_d1[i];
    for (int i = tid; i < 768; i += NT) smf[FI_AB + 2048 + i] = W_d2[i];
    if (tid < 32) smf[FI_AB + 2816 + tid] = b_d1[tid];
    if (tid < 24) smf[FI_AB + 2848 + tid] = b_d2[tid];
    __syncthreads();

    for (int idx = tid; idx < 1024; idx += NT) {
        int b = idx >> 5, j = idx & 31;
        float a = smf[FI_AB + 2816 + j];
        #pragma unroll 8
        for (int k = 0; k < 64; ++k)
            a += smf[FI_H2F + b * 66 + k] * smf[FI_AB + j * 64 + k];
        smf[FI_AB + 2880 + b * 32 + j] = fmaxf(a, 0.f);
    }
    __syncthreads();
    for (int idx = tid; idx < 768; idx += NT) {
        int b = idx / 24, o = idx - b * 24;
        float a = smf[FI_AB + 2848 + o];
        #pragma unroll 8
        for (int j = 0; j < 32; ++j)
            a += smf[FI_AB + 2880 + b * 32 + j] * smf[FI_AB + 2048 + o * 32 + j];
        out[(size_t)(b0 + b) * 24 + o] = a;
    }
#else
    // ================= FMA fallback (R4, 4786us) =================
    float* sm = (float*)smraw;
    const int tid  = threadIdx.x;
    const int lane = tid & 31;
    const int wrp  = tid >> 5;
    const int hid  = ((wrp & 1) << 5) | lane;
    const int bg   = wrp >> 1;
    const int b0   = blockIdx.x * 32;
    const int octh = ((bg + hid) & 3) << 3;
    const int hid4 = hid << 2;

    for (int i = tid; i < 64 * 256; i += NT) {
        int k = i >> 8, r = i & 255;
        int g = r >> 6, h = r & 63;
        sm[WT1_O + k * 256 + h * 4 + g] = W_hh1[r * 64 + k];
    }
    for (int i = tid; i < 64 * 256; i += NT) {
        int k = i >> 8, r = i & 255;
        int g = r >> 6, h = r & 63;
        sm[WT2_O + k * 256 + h * 4 + g] = W_ih2[r * 64 + k];
    }
    for (int i = tid; i < 64 * 256; i += NT) {
        int k = i >> 8, r = i & 255;
        int g = r >> 6, h = r & 63;
        sm[WT2_O + (64 + k) * 256 + h * 4 + g] = W_hh2[r * 64 + k];
    }
    for (int i = tid; i < 256; i += NT) {
        sm[B1_O + i]  = b_ih1[i] + b_hh1[i];
        sm[B2_O + i]  = b_ih2[i] + b_hh2[i];
        sm[WI1_O + i] = W_ih1[i];
    }
    for (int i = tid; i < 128 * 32; i += NT) sm[HA_O + i] = 0.f;
    {
        #pragma unroll
        for (int it = 0; it < 2; ++it) {
            int i = tid + it * NT;
            int row = i >> 4, q = (i & 15) << 2;
            float4 v = *(const float4*)(x + (size_t)(b0 + row) * SEQ + q);
            sm[XT_O + (q + 0) * 34 + row] = v.x;
            sm[XT_O + (q + 1) * 34 + row] = v.y;
            sm[XT_O + (q + 2) * 34 + row] = v.z;
            sm[XT_O + (q + 3) * 34 + row] = v.w;
        }
    }
    __syncthreads();

    u64   acc1[4][4], acc2[4][4];
    float c1[8], c2[8];
    #pragma unroll
    for (int j = 0; j < 8; ++j) { c1[j] = 0.f; c2[j] = 0.f; }

    float* h1dst = &sm[HA_O + hid * 32 + octh];
    float* h2dst = &sm[HA_O + (64 + hid) * 32 + octh];

    {
        u64 xp[4];
        #pragma unroll
        for (int p = 0; p < 4; ++p)
            xp[p] = *(const u64*)&sm[XT_O + 0 * 34 + bg * 8 + 2 * p];
        #pragma unroll
        for (int g = 0; g < 4; ++g) {
            u64 sb = splat2f(sm[B1_O + g * 64 + hid]);
            u64 sw = splat2f(sm[WI1_O + g * 64 + hid]);
            #pragma unroll
            for (int p = 0; p < 4; ++p) { acc1[g][p] = sb; fma2(acc1[g][p], sw, xp[p]); }
        }
        pointwise_f(acc1, c1, h1dst);
    }
    __syncthreads();

    for (int t = 0; t < SEQ; ++t) {
        if (((t + 1) & 63) == 0 && (t + 1) < SEQ) {
            int base = t + 1;
            #pragma unroll
            for (int it = 0; it < 2; ++it) {
                int i = tid + it * NT;
                int row = i >> 4, q = (i & 15) << 2;
                float4 v = *(const float4*)(x + (size_t)(b0 + row) * SEQ + base + q);
                sm[XT_O + (q + 0) * 34 + row] = v.x;
                sm[XT_O + (q + 1) * 34 + row] = v.y;
                sm[XT_O + (q + 2) * 34 + row] = v.z;
                sm[XT_O + (q + 3) * 34 + row] = v.w;
            }
            __syncthreads();
        }
        const int tt = ((t + 1) < SEQ ? (t + 1) : t) & 63;

        #pragma unroll
        for (int g = 0; g < 4; ++g) {
            u64 s = splat2f(sm[B2_O + g * 64 + hid]);
            #pragma unroll
            for (int p = 0; p < 4; ++p) acc2[g][p] = s;
        }
        {
            u64 xp[4];
            #pragma unroll
            for (int p = 0; p < 4; ++p)
                xp[p] = *(const u64*)&sm[XT_O + tt * 34 + bg * 8 + 2 * p];
            #pragma unroll
            for (int g = 0; g < 4; ++g) {
                u64 sb = splat2f(sm[B1_O + g * 64 + hid]);
                u64 sw = splat2f(sm[WI1_O + g * 64 + hid]);
                #pragma unroll
                for (int p = 0; p < 4; ++p) { acc1[g][p] = sb; fma2(acc1[g][p], sw, xp[p]); }
            }
        }

        {
            u64 h1r[2][4], h2r[2][4];
            float4 w1r[2], w2ar[2], w2br[2];
            LOADK(0, 0);
            #pragma unroll 2
            for (int k = 0; k < 64; ++k) {
                const int cur = k & 1;
                if (k < 63) LOADK(k + 1, cur ^ 1);
                FMAK(cur);
            }
        }
        __syncthreads();

        pointwise_f(acc2, c2, h2dst);
        if (t + 1 < SEQ) pointwise_f(acc1, c1, h1dst);
        __syncthreads();
    }

    for (int i = tid; i < 32 * 64; i += NT) sm[XT_O + i] = W_d1[i];
    for (int i = tid; i < 24 * 32; i += NT) sm[HW_O + i] = W_d2[i];
    if (tid < 32) sm[HW_O + 768 + tid] = b_d1[tid];
    if (tid < 24) sm[HW_O + 800 + tid] = b_d2[tid];
    __syncthreads();

    for (int idx = tid; idx < 32 * 32; idx += NT) {
        int b = idx >> 5, j = idx & 31;
        int ob = b >> 3, bl = b & 7;
        float a = sm[HW_O + 768 + j];
        #pragma unroll 8
        for (int k = 0; k < 64; ++k) {
            float hv = sm[HA_O + (64 + k) * 32 + (((ob + k) & 3) << 3) + bl];
            a += hv * sm[XT_O + j * 64 + k];
        }
        sm[HA_O + b * 32 + j] = fmaxf(a, 0.f);
    }
    __syncthreads();
    for (int idx = tid; idx < 32 * 24; idx += NT) {
        int b = idx / 24, o = idx - b * 24;
        float a = sm[HW_O + 800 + o];
        #pragma unroll 8
        for (int j = 0; j < 32; ++j)
            a += sm[HA_O + b * 32 + j] * sm[HW_O + o * 32 + j];
        out[(size_t)(b0 + b) * 24 + o] = a;
    }
#endif
}

extern "C" void kernel_launch(void* const* d_in, const int* in_sizes, int n_in,
                              void* d_out, int out_size)
{
    const float* x     = (const float*)d_in[0];
    const float* W_ih1 = (const float*)d_in[1];
    const float* W_hh1 = (const float*)d_in[2];
    const float* b_ih1 = (const float*)d_in[3];
    const float* b_hh1 = (const float*)d_in[4];
    const float* W_ih2 = (const float*)d_in[5];
    const float* W_hh2 = (const float*)d_in[6];
    const float* b_ih2 = (const float*)d_in[7];
    const float* b_hh2 = (const float*)d_in[8];
    const float* W_d1  = (const float*)d_in[9];
    const float* b_d1  = (const float*)d_in[10];
    const float* W_d2  = (const float*)d_in[11];
    const float* b_d2  = (const float*)d_in[12];
    float* out = (float*)d_out;

    cudaFuncSetAttribute(lstm_kernel,
                         cudaFuncAttributeMaxDynamicSharedMemorySize, SM_BYTES_HOST);
    lstm_kernel<<<NBLK, NT, SM_BYTES_HOST>>>(
        x, W_ih1, W_hh1, b_ih1, b_hh1, W_ih2, W_hh2, b_ih2, b_hh2,
        W_d1, b_d1, W_d2, b_d2, out);
}

// round 16
// speedup vs baseline: 1.0130x; 1.0010x over previous
#include <cuda_runtime.h>
#include <cuda_bf16.h>
#include <cstdint>

#define NT   256
#define NBLK 128
#define SEQ  512

#if defined(__CUDA_ARCH_FEAT_SM103_ALL)
#define TC_PATH 1
#else
#define TC_PATH 0
#endif

#define SM_BYTES_HOST 228096

typedef unsigned long long u64;

static __device__ __forceinline__ float sigf(float x) {
    return __fdividef(1.f, 1.f + __expf(-x));
}
static __device__ __forceinline__ float tanhf_(float x) {
    float xx = fmaxf(x, -30.f);
    float e  = __expf(-2.f * xx);
    return __fdividef(1.f - e, 1.f + e);
}

extern __shared__ char smraw[];

#if TC_PATH
// ================= tcgen05 path =================
#define IDESC 0x8080490u  // f16 MMA: F32 acc, bf16 a/b, M=128, N=32

#define SB_MBAR  0
#define SB_TMEMP 16
#define FI_WI1 8
#define FI_B1  264
#define FI_B2  520
#define FI_XT  776            // 16 x 36
#define FI_H2F 1352           // 32 x 66
#define FI_AB  3464           // 256 x 36 activated-exchange buffer
#define SB_T0  51200          // 8 bf16 tiles x 4KB (SW128 32x128B)
// tiles: 0 H1A_hi 1 H1A_lo 2 H1B_hi 3 H1B_lo 4 H2A_hi 5 H2A_lo 6 H2B_hi 7 H2B_lo

static __device__ __forceinline__ uint32_t smem_u32(const void* p) {
    uint32_t a;
    asm("{ .reg .u64 t; cvta.to.shared.u64 t, %1; cvt.u32.u64 %0, t; }" : "=r"(a) : "l"(p));
    return a;
}
static __device__ __forceinline__ uint32_t elect1() {
    uint32_t p;
    asm volatile("{ .reg .pred p; elect.sync _|p, 0xFFFFFFFF; selp.b32 %0,1,0,p; }" : "=r"(p));
    return p;
}
static __device__ __forceinline__ uint64_t mkdesc(uint32_t sa) {
    const uint64_t base = (2ULL << 61) | (1ULL << 46) | (64ULL << 32) | (1ULL << 16);
    return base | ((uint64_t)(sa >> 4) & 0x3FFF);
}
static __device__ __forceinline__ void mma_ts(uint32_t d, uint32_t a, uint64_t bd) {
    asm volatile("{ .reg .pred p; setp.eq.u32 p,1,1;\n\t"
        "tcgen05.mma.cta_group::1.kind::f16 [%0], [%1], %2, %3, {%4,%4,%4,%4}, p; }"
        :: "r"(d), "r"(a), "l"(bd), "r"(IDESC), "r"(0u) : "memory");
}
static __device__ __forceinline__ void mma_ts0(uint32_t d, uint32_t a, uint64_t bd) {
    asm volatile("{ .reg .pred p; setp.eq.u32 p,1,0;\n\t"
        "tcgen05.mma.cta_group::1.kind::f16 [%0], [%1], %2, %3, {%4,%4,%4,%4}, p; }"
        :: "r"(d), "r"(a), "l"(bd), "r"(IDESC), "r"(0u) : "memory");
}
#define TC_ALLOC(sa,n)  asm volatile("tcgen05.alloc.cta_group::1.sync.aligned.shared::cta.b32 [%0], %1;" :: "r"(sa), "r"(n) : "memory")
#define TC_DEALLOC(t,n) asm volatile("tcgen05.dealloc.cta_group::1.sync.aligned.b32 %0, %1;" :: "r"(t), "r"(n))
#define TC_RELINQ()     asm volatile("tcgen05.relinquish_alloc_permit.cta_group::1.sync.aligned;")
#define TC_WST()        asm volatile("tcgen05.wait::st.sync.aligned;" ::: "memory")
#define TC_WLD()        asm volatile("tcgen05.wait::ld.sync.aligned;" ::: "memory")
#define TC_FB()         asm volatile("tcgen05.fence::before_thread_sync;" ::: "memory")
#define TC_FA()         asm volatile("tcgen05.fence::after_thread_sync;" ::: "memory")
#define TC_COMMIT(mb)   asm volatile("tcgen05.commit.cta_group::1.mbarrier::arrive::one.shared::cluster.b64 [%0];" :: "r"(mb) : "memory")
#define FENCE_ASYNC()   asm volatile("fence.proxy.async.shared::cta;" ::: "memory")
#define MBAR_INIT(mb,n) asm volatile("mbarrier.init.shared.b64 [%0], %1;" :: "r"(mb), "r"(n) : "memory")
#define MBAR_WAIT(mb,par) do { uint32_t _m=(mb),_p=(par),_d; \
    asm volatile("{ .reg .pred p; mbarrier.try_wait.parity.acquire.cta.shared::cta.b64 p, [%1], %2; selp.b32 %0,1,0,p; }" : "=r"(_d) : "r"(_m), "r"(_p) : "memory"); \
    if (!_d) asm volatile("{ .reg .pred P1; WL%=: mbarrier.try_wait.parity.acquire.cta.shared::cta.b64 P1, [%0], %1, 0x989680; @P1 bra.uni WD%=; bra.uni WL%=; WD%=: }" :: "r"(_m), "r"(_p) : "memory"); \
    } while (0)

#define R32(r) "r"((r)[0]),"r"((r)[1]),"r"((r)[2]),"r"((r)[3]),"r"((r)[4]),"r"((r)[5]),"r"((r)[6]),"r"((r)[7]),\
"r"((r)[8]),"r"((r)[9]),"r"((r)[10]),"r"((r)[11]),"r"((r)[12]),"r"((r)[13]),"r"((r)[14]),"r"((r)[15]),\
"r"((r)[16]),"r"((r)[17]),"r"((r)[18]),"r"((r)[19]),"r"((r)[20]),"r"((r)[21]),"r"((r)[22]),"r"((r)[23]),\
"r"((r)[24]),"r"((r)[25]),"r"((r)[26]),"r"((r)[27]),"r"((r)[28]),"r"((r)[29]),"r"((r)[30]),"r"((r)[31])
#define W32(r) "=r"((r)[0]),"=r"((r)[1]),"=r"((r)[2]),"=r"((r)[3]),"=r"((r)[4]),"=r"((r)[5]),"=r"((r)[6]),"=r"((r)[7]),\
"=r"((r)[8]),"=r"((r)[9]),"=r"((r)[10]),"=r"((r)[11]),"=r"((r)[12]),"=r"((r)[13]),"=r"((r)[14]),"=r"((r)[15]),\
"=r"((r)[16]),"=r"((r)[17]),"=r"((r)[18]),"=r"((r)[19]),"=r"((r)[20]),"=r"((r)[21]),"=r"((r)[22]),"=r"((r)[23]),\
"=r"((r)[24]),"=r"((r)[25]),"=r"((r)[26]),"=r"((r)[27]),"=r"((r)[28]),"=r"((r)[29]),"=r"((r)[30]),"=r"((r)[31])

#define STTM32(a, r) asm volatile("tcgen05.st.sync.aligned.32x32b.x32.b32 [%0], {%1,%2,%3,%4,%5,%6,%7,%8,%9,%10,%11,%12,%13,%14,%15,%16,%17,%18,%19,%20,%21,%22,%23,%24,%25,%26,%27,%28,%29,%30,%31,%32};" :: "r"(a), R32(r) : "memory")
#define LDTM32(r, a) asm volatile("tcgen05.ld.sync.aligned.32x32b.x32.b32 {%0,%1,%2,%3,%4,%5,%6,%7,%8,%9,%10,%11,%12,%13,%14,%15,%16,%17,%18,%19,%20,%21,%22,%23,%24,%25,%26,%27,%28,%29,%30,%31}, [%32];" : W32(r) : "r"(a))

static __device__ __forceinline__ void a_row(const float* g, uint32_t thi, uint32_t tlo) {
    uint32_t whi[32], wlo[32];
    #pragma unroll
    for (int i = 0; i < 32; ++i) {
        float a = g[2 * i], b = g[2 * i + 1];
        __nv_bfloat16 ah = __float2bfloat16(a), bh = __float2bfloat16(b);
        __nv_bfloat16 al = __float2bfloat16(a - __bfloat162float(ah));
        __nv_bfloat16 bl = __float2bfloat16(b - __bfloat162float(bh));
        whi[i] = (uint32_t)__bfloat16_as_ushort(ah) | ((uint32_t)__bfloat16_as_ushort(bh) << 16);
        wlo[i] = (uint32_t)__bfloat16_as_ushort(al) | ((uint32_t)__bfloat16_as_ushort(bl) << 16);
    }
    STTM32(thi, whi); STTM32(tlo, wlo);
}

// 24 MMAs: D(dbase) (+)= A(hi/lo) x B(hi/lo), 2 tiles x 4 kc x 3 passes.
// init: first MMA per D tile overwrites (enable_d = 0).
static __device__ __forceinline__ void mma_blk(uint32_t tb, uint32_t dbase,
        uint32_t ahi, uint32_t alo, uint64_t dh, uint64_t dl, bool init) {
    #pragma unroll
    for (int tl = 0; tl < 2; ++tl) {
        uint32_t d = tb + dbase + tl * 32, ah = tb + ahi + tl * 32, al = tb + alo + tl * 32;
        #pragma unroll
        for (int kc = 0; kc < 4; ++kc) {
            if (kc == 0 && init) mma_ts0(d, ah, dh);
            else                 mma_ts(d, ah + kc * 8, dh + kc * 2);
            mma_ts(d, al + kc * 8, dh + kc * 2);
            mma_ts(d, ah + kc * 8, dl + kc * 2);
        }
    }
}

// LDTM one D half, fold bias (+ optional x*w), activate (gate-uniform per warp),
// scatter activated values to AB exchange buffer.
static __device__ __forceinline__ void act(float* smf, uint32_t tmaddr, int grow,
                                           float bb, float wi, const float* xrow) {
    uint32_t zr[32];
    LDTM32(zr, tmaddr);
    TC_WLD();
    float* zp = smf + FI_AB + grow * 36;
    const int gate = grow >> 6;
    if (gate == 2) {
        #pragma unroll
        for (int q = 0; q < 8; ++q) {
            float4 xv = xrow ? *(const float4*)&xrow[4 * q] : make_float4(0.f, 0.f, 0.f, 0.f);
            float4 o;
            o.x = tanhf_(__uint_as_float(zr[4 * q + 0]) + fmaf(wi, xv.x, bb));
            o.y = tanhf_(__uint_as_float(zr[4 * q + 1]) + fmaf(wi, xv.y, bb));
            o.z = tanhf_(__uint_as_float(zr[4 * q + 2]) + fmaf(wi, xv.z, bb));
            o.w = tanhf_(__uint_as_float(zr[4 * q + 3]) + fmaf(wi, xv.w, bb));
            *(float4*)&zp[4 * q] = o;
        }
    } else {
        #pragma unroll
        for (int q = 0; q < 8; ++q) {
            float4 xv = xrow ? *(const float4*)&xrow[4 * q] : make_float4(0.f, 0.f, 0.f, 0.f);
            float4 o;
            o.x = sigf(__uint_as_float(zr[4 * q + 0]) + fmaf(wi, xv.x, bb));
            o.y = sigf(__uint_as_float(zr[4 * q + 1]) + fmaf(wi, xv.y, bb));
            o.z = sigf(__uint_as_float(zr[4 * q + 2]) + fmaf(wi, xv.z, bb));
            o.w = sigf(__uint_as_float(zr[4 * q + 3]) + fmaf(wi, xv.w, bb));
            *(float4*)&zp[4 * q] = o;
        }
    }
}

// cell update from activated gates; write h bf16 hi/lo into SW128 tiles.
static __device__ __forceinline__ void upd(float* smf, int hid, int bq, float* c,
                                           char* bhi, char* blo, float* hf) {
    const float* ab = smf + FI_AB + bq * 8;
    float ai[8], af[8], ag[8], ao[8];
    *(float4*)&ai[0] = *(const float4*)&ab[hid * 36];
    *(float4*)&ai[4] = *(const float4*)&ab[hid * 36 + 4];
    *(float4*)&af[0] = *(const float4*)&ab[(64 + hid) * 36];
    *(float4*)&af[4] = *(const float4*)&ab[(64 + hid) * 36 + 4];
    *(float4*)&ag[0] = *(const float4*)&ab[(128 + hid) * 36];
    *(float4*)&ag[4] = *(const float4*)&ab[(128 + hid) * 36 + 4];
    *(float4*)&ao[0] = *(const float4*)&ab[(192 + hid) * 36];
    *(float4*)&ao[4] = *(const float4*)&ab[(192 + hid) * 36 + 4];
    #pragma unroll
    for (int j = 0; j < 8; ++j) {
        float cc = fmaf(af[j], c[j], ai[j] * ag[j]);
        c[j] = cc;
        float h = ao[j] * tanhf_(cc);
        int b = bq * 8 + j;
        __nv_bfloat16 hh = __float2bfloat16(h);
        __nv_bfloat16 hl = __float2bfloat16(h - __bfloat162float(hh));
        int off = b * 128 + hid * 2, sw = off ^ ((off >> 3) & 0x70);
        *(__nv_bfloat16*)(bhi + sw) = hh;
        *(__nv_bfloat16*)(blo + sw) = hl;
        if (hf) hf[b * 66 + hid] = h;
    }
}
#else
// ================= FMA fallback helpers (R4) =================
static __device__ __forceinline__ u64 splat2f(float v) {
    u64 r; unsigned u = __float_as_uint(v);
    asm("mov.b64 %0, {%1, %1};" : "=l"(r) : "r"(u));
    return r;
}
static __device__ __forceinline__ void fma2(u64& d, u64 a, u64 b) {
    asm("fma.rn.f32x2 %0, %1, %2, %0;" : "+l"(d) : "l"(a), "l"(b));
}
static __device__ __forceinline__ float lo32(u64 v) { return __uint_as_float((unsigned)v); }
static __device__ __forceinline__ float hi32(u64 v) { return __uint_as_float((unsigned)(v >> 32)); }

#define WT1_O 0
#define WT2_O (WT1_O + 64 * 256)
#define HA_O  (WT2_O + 128 * 256)
#define XT_O  (HA_O + 128 * 32)
#define B1_O  (XT_O + 64 * 34)
#define B2_O  (B1_O + 256)
#define WI1_O (B2_O + 256)
#define HW_O  (WI1_O + 256)

static __device__ __forceinline__ void pointwise_f(const u64 acc[4][4], float c[8], float* hdst) {
    float hv[8];
    #pragma unroll
    for (int p = 0; p < 4; ++p) {
        #pragma unroll
        for (int q = 0; q < 2; ++q) {
            int j = 2 * p + q;
            float zi = q ? hi32(acc[0][p]) : lo32(acc[0][p]);
            float zf = q ? hi32(acc[1][p]) : lo32(acc[1][p]);
            float zg = q ? hi32(acc[2][p]) : lo32(acc[2][p]);
            float zo = q ? hi32(acc[3][p]) : lo32(acc[3][p]);
            float cc = sigf(zf) * c[j] + sigf(zi) * tanhf_(zg);
            c[j] = cc;
            hv[j] = sigf(zo) * tanhf_(cc);
        }
    }
    *(float4*)&hdst[0] = make_float4(hv[0], hv[1], hv[2], hv[3]);
    *(float4*)&hdst[4] = make_float4(hv[4], hv[5], hv[6], hv[7]);
}

#define LOADK(K, b) { \
    int ha = HA_O + ((K) << 5) + (((bg + (K)) & 3) << 3); \
    ulonglong2 q0 = *(const ulonglong2*)&sm[ha]; \
    ulonglong2 q1 = *(const ulonglong2*)&sm[ha + 4]; \
    ulonglong2 q2 = *(const ulonglong2*)&sm[ha + 2048]; \
    ulonglong2 q3 = *(const ulonglong2*)&sm[ha + 2048 + 4]; \
    h1r[b][0] = q0.x; h1r[b][1] = q0.y; h1r[b][2] = q1.x; h1r[b][3] = q1.y; \
    h2r[b][0] = q2.x; h2r[b][1] = q2.y; h2r[b][2] = q3.x; h2r[b][3] = q3.y; \
    w1r[b]  = *(const float4*)&sm[WT1_O + (K) * 256 + hid4]; \
    w2ar[b] = *(const float4*)&sm[WT2_O + (K) * 256 + hid4]; \
    w2br[b] = *(const float4*)&sm[WT2_O + ((K) + 64) * 256 + hid4]; }

#define FMA_G(g, wv, accarr, hparr) { \
    u64 s = splat2f(wv); \
    fma2(accarr[g][0], s, hparr[0]); fma2(accarr[g][1], s, hparr[1]); \
    fma2(accarr[g][2], s, hparr[2]); fma2(accarr[g][3], s, hparr[3]); }

#define FMAK(b) { \
    FMA_G(0, w1r[b].x,  acc1, h1r[b]); FMA_G(1, w1r[b].y,  acc1, h1r[b]); \
    FMA_G(2, w1r[b].z,  acc1, h1r[b]); FMA_G(3, w1r[b].w,  acc1, h1r[b]); \
    FMA_G(0, w2ar[b].x, acc2, h1r[b]); FMA_G(1, w2ar[b].y, acc2, h1r[b]); \
    FMA_G(2, w2ar[b].z, acc2, h1r[b]); FMA_G(3, w2ar[b].w, acc2, h1r[b]); \
    FMA_G(0, w2br[b].x, acc2, h2r[b]); FMA_G(1, w2br[b].y, acc2, h2r[b]); \
    FMA_G(2, w2br[b].z, acc2, h2r[b]); FMA_G(3, w2br[b].w, acc2, h2r[b]); }
#endif

__global__ void __launch_bounds__(NT, 1)
lstm_kernel(const float* __restrict__ x,
            const float* __restrict__ W_ih1, const float* __restrict__ W_hh1,
            const float* __restrict__ b_ih1, const float* __restrict__ b_hh1,
            const float* __restrict__ W_ih2, const float* __restrict__ W_hh2,
            const float* __restrict__ b_ih2, const float* __restrict__ b_hh2,
            const float* __restrict__ W_d1, const float* __restrict__ b_d1,
            const float* __restrict__ W_d2, const float* __restrict__ b_d2,
            float* __restrict__ out)
{
#if TC_PATH
    char* smc = smraw;
    float* smf = (float*)smc;
    const int tid = threadIdx.x, lane = tid & 31, wrp = tid >> 5;
    const int wg = wrp >> 2, sub = wrp & 3;
    const int grow = wg * 128 + sub * 32 + lane;
    const int b0 = blockIdx.x * 32;
    const uint32_t sbase = smem_u32(smc);
    const uint32_t woff = (uint32_t)sub << 21;
    const uint32_t mb1 = sbase + SB_MBAR, mb2 = sbase + SB_MBAR + 8;

    if (wrp == 0) TC_ALLOC(sbase + SB_TMEMP, 512);
    __syncthreads();
    uint32_t tb;
    asm volatile("ld.shared.b32 %0, [%1];" : "=r"(tb) : "r"(sbase + SB_TMEMP));
    if (tid == 0) { MBAR_INIT(mb1, 1); MBAR_INIT(mb2, 1); }

    for (int i = tid; i < 256; i += NT) {
        smf[FI_WI1 + i] = W_ih1[i];
        smf[FI_B1 + i] = b_ih1[i] + b_hh1[i];
        smf[FI_B2 + i] = b_ih2[i] + b_hh2[i];
    }
    for (int i = tid; i < 8192; i += NT) ((uint32_t*)(smc + SB_T0))[i] = 0;

    a_row(W_hh1 + grow * 64, tb + 128 + wg * 32 + woff, tb + 192 + wg * 32 + woff);
    a_row(W_ih2 + grow * 64, tb + 256 + wg * 32 + woff, tb + 320 + wg * 32 + woff);
    a_row(W_hh2 + grow * 64, tb + 384 + wg * 32 + woff, tb + 448 + wg * 32 + woff);
    TC_WST();
    TC_FB();
    FENCE_ASYNC();
    __syncthreads();

    uint64_t dt[8];
    #pragma unroll
    for (int i = 0; i < 8; ++i) dt[i] = mkdesc(sbase + SB_T0 + i * 4096);

    float c1[8], c2[8];
    #pragma unroll
    for (int j = 0; j < 8; ++j) { c1[j] = 0.f; c2[j] = 0.f; }
    const int hid = tid & 63, bq = tid >> 6;
    const float wi = smf[FI_WI1 + grow], bb1 = smf[FI_B1 + grow], bb2 = smf[FI_B2 + grow];

    // prologue: D1 = W_hh1 * 0 (enable0 over zeroed tile), commit mb1;
    //           D2 = W_hh2 * 0 (enable0), no commit (mb2 comes with L2ih(0)).
    if (wrp == 0) {
        TC_FA();
        if (elect1()) {
            mma_blk(tb, 0, 128, 192, dt[2], dt[3], true);
            TC_COMMIT(mb1);
            mma_blk(tb, 64, 384, 448, dt[6], dt[7], true);
        }
    }

    for (int t = 0; t < SEQ; ++t) {
        if ((t & 15) == 0) {
            for (int i = tid; i < 512; i += NT) {
                int row = i >> 4, tq = i & 15;
                smf[FI_XT + tq * 36 + row] = x[(size_t)(b0 + row) * SEQ + t + tq];
            }
            __syncthreads();
        }
        const int tt = t & 15, ph = t & 1;
        const int h1c = ph ? 2 : 0;   // h1 tile written this step
        const int h2c = ph ? 6 : 4;   // h2 tile written this step

        // P1: z1 -> activated gates
        MBAR_WAIT(mb1, ph);
        TC_FA();
        act(smf, tb + wg * 32, grow, bb1, wi, &smf[FI_XT + tt * 36]);
        __syncthreads();

        // P2: update h1
        upd(smf, hid, bq, c1, smc + SB_T0 + h1c * 4096, smc + SB_T0 + (h1c + 1) * 4096, nullptr);
        FENCE_ASYNC();
        __syncthreads();

        // I1: L2ih(t)*h1(t) -> D2 (accumulate), commit mb2;
        //     L1(t+1)*h1(t) -> D1 (enable0 overwrite), commit mb1.
        if (wrp == 0) {
            TC_FA();
            if (elect1()) {
                mma_blk(tb, 64, 256, 320, dt[h1c], dt[h1c + 1], false);
                TC_COMMIT(mb2);
                if (t + 1 < SEQ) {
                    mma_blk(tb, 0, 128, 192, dt[h1c], dt[h1c + 1], true);
                    TC_COMMIT(mb1);
                }
            }
        }

        // P4: z2 -> activated gates
        MBAR_WAIT(mb2, ph);
        TC_FA();
        act(smf, tb + 64 + wg * 32, grow, bb2, 0.f, nullptr);
        __syncthreads();

        // P5: update h2
        upd(smf, hid, bq, c2, smc + SB_T0 + h2c * 4096, smc + SB_T0 + (h2c + 1) * 4096,
            (t == SEQ - 1) ? &smf[FI_H2F] : nullptr);
        FENCE_ASYNC();
        __syncthreads();

        // I2: L2hh(t)*h2(t) -> D2 (enable0 overwrite), no commit yet.
        if (t + 1 < SEQ && wrp == 0) {
            TC_FA();
            if (elect1())
                mma_blk(tb, 64, 384, 448, dt[h2c], dt[h2c + 1], true);
        }
    }

    if (wrp == 0) { TC_RELINQ(); TC_DEALLOC(tb, 512); }

    // dense head on fp32 h2[511]
    for (int i = tid; i < 2048; i += NT) smf[FI_AB + i] = W_d1[i];
    for (int i = tid; i < 768; i += NT) smf[FI_AB + 2048 + i] = W_d2[i];
    if (tid < 32) smf[FI_AB + 2816 + tid] = b_d1[tid];
    if (tid < 24) smf[FI_AB + 2848 + tid] = b_d2[tid];
    __syncthreads();

    for (int idx = tid; idx < 1024; idx += NT) {
        int b = idx >> 5, j = idx & 31;
        float a = smf[FI_AB + 2816 + j];
        #pragma unroll 8
        for (int k = 0; k < 64; ++k)
            a += smf[FI_H2F + b * 66 + k] * smf[FI_AB + j * 64 + k];
        smf[FI_AB + 2880 + b * 32 + j] = fmaxf(a, 0.f);
    }
    __syncthreads();
    for (int idx = tid; idx < 768; idx += NT) {
        int b = idx / 24, o = idx - b * 24;
        float a = smf[FI_AB + 2848 + o];
        #pragma unroll 8
        for (int j = 0; j < 32; ++j)
            a += smf[FI_AB + 2880 + b * 32 + j] * smf[FI_AB + 2048 + o * 32 + j];
        out[(size_t)(b0 + b) * 24 + o] = a;
    }
#else
    // ================= FMA fallback (R4, 4786us) =================
    float* sm = (float*)smraw;
    const int tid  = threadIdx.x;
    const int lane = tid & 31;
    const int wrp  = tid >> 5;
    const int hid  = ((wrp & 1) << 5) | lane;
    const int bg   = wrp >> 1;
    const int b0   = blockIdx.x * 32;
    const int octh = ((bg + hid) & 3) << 3;
    const int hid4 = hid << 2;

    for (int i = tid; i < 64 * 256; i += NT) {
        int k = i >> 8, r = i & 255;
        int g = r >> 6, h = r & 63;
        sm[WT1_O + k * 256 + h * 4 + g] = W_hh1[r * 64 + k];
    }
    for (int i = tid; i < 64 * 256; i += NT) {
        int k = i >> 8, r = i & 255;
        int g = r >> 6, h = r & 63;
        sm[WT2_O + k * 256 + h * 4 + g] = W_ih2[r * 64 + k];
    }
    for (int i = tid; i < 64 * 256; i += NT) {
        int k = i >> 8, r = i & 255;
        int g = r >> 6, h = r & 63;
        sm[WT2_O + (64 + k) * 256 + h * 4 + g] = W_hh2[r * 64 + k];
    }
    for (int i = tid; i < 256; i += NT) {
        sm[B1_O + i]  = b_ih1[i] + b_hh1[i];
        sm[B2_O + i]  = b_ih2[i] + b_hh2[i];
        sm[WI1_O + i] = W_ih1[i];
    }
    for (int i = tid; i < 128 * 32; i += NT) sm[HA_O + i] = 0.f;
    {
        #pragma unroll
        for (int it = 0; it < 2; ++it) {
            int i = tid + it * NT;
            int row = i >> 4, q = (i & 15) << 2;
            float4 v = *(const float4*)(x + (size_t)(b0 + row) * SEQ + q);
            sm[XT_O + (q + 0) * 34 + row] = v.x;
            sm[XT_O + (q + 1) * 34 + row] = v.y;
            sm[XT_O + (q + 2) * 34 + row] = v.z;
            sm[XT_O + (q + 3) * 34 + row] = v.w;
        }
    }
    __syncthreads();

    u64   acc1[4][4], acc2[4][4];
    float c1[8], c2[8];
    #pragma unroll
    for (int j = 0; j < 8; ++j) { c1[j] = 0.f; c2[j] = 0.f; }

    float* h1dst = &sm[HA_O + hid * 32 + octh];
    float* h2dst = &sm[HA_O + (64 + hid) * 32 + octh];

    {
        u64 xp[4];
        #pragma unroll
        for (int p = 0; p < 4; ++p)
            xp[p] = *(const u64*)&sm[XT_O + 0 * 34 + bg * 8 + 2 * p];
        #pragma unroll
        for (int g = 0; g < 4; ++g) {
            u64 sb = splat2f(sm[B1_O + g * 64 + hid]);
            u64 sw = splat2f(sm[WI1_O + g * 64 + hid]);
            #pragma unroll
            for (int p = 0; p < 4; ++p) { acc1[g][p] = sb; fma2(acc1[g][p], sw, xp[p]); }
        }
        pointwise_f(acc1, c1, h1dst);
    }
    __syncthreads();

    for (int t = 0; t < SEQ; ++t) {
        if (((t + 1) & 63) == 0 && (t + 1) < SEQ) {
            int base = t + 1;
            #pragma unroll
            for (int it = 0; it < 2; ++it) {
                int i = tid + it * NT;
                int row = i >> 4, q = (i & 15) << 2;
                float4 v = *(const float4*)(x + (size_t)(b0 + row) * SEQ + base + q);
                sm[XT_O + (q + 0) * 34 + row] = v.x;
                sm[XT_O + (q + 1) * 34 + row] = v.y;
                sm[XT_O + (q + 2) * 34 + row] = v.z;
                sm[XT_O + (q + 3) * 34 + row] = v.w;
            }
            __syncthreads();
        }
        const int tt = ((t + 1) < SEQ ? (t + 1) : t) & 63;

        #pragma unroll
        for (int g = 0; g < 4; ++g) {
            u64 s = splat2f(sm[B2_O + g * 64 + hid]);
            #pragma unroll
            for (int p = 0; p < 4; ++p) acc2[g][p] = s;
        }
        {
            u64 xp[4];
            #pragma unroll
            for (int p = 0; p < 4; ++p)
                xp[p] = *(const u64*)&sm[XT_O + tt * 34 + bg * 8 + 2 * p];
            #pragma unroll
            for (int g = 0; g < 4; ++g) {
                u64 sb = splat2f(sm[B1_O + g * 64 + hid]);
                u64 sw = splat2f(sm[WI1_O + g * 64 + hid]);
                #pragma unroll
                for (int p = 0; p < 4; ++p) { acc1[g][p] = sb; fma2(acc1[g][p], sw, xp[p]); }
            }
        }

        {
            u64 h1r[2][4], h2r[2][4];
            float4 w1r[2], w2ar[2], w2br[2];
            LOADK(0, 0);
            #pragma unroll 2
            for (int k = 0; k < 64; ++k) {
                const int cur = k & 1;
                if (k < 63) LOADK(k + 1, cur ^ 1);
                FMAK(cur);
            }
        }
        __syncthreads();

        pointwise_f(acc2, c2, h2dst);
        if (t + 1 < SEQ) pointwise_f(acc1, c1, h1dst);
        __syncthreads();
    }

    for (int i = tid; i < 32 * 64; i += NT) sm[XT_O + i] = W_d1[i];
    for (int i = tid; i < 24 * 32; i += NT) sm[HW_O + i] = W_d2[i];
    if (tid < 32) sm[HW_O + 768 + tid] = b_d1[tid];
    if (tid < 24) sm[HW_O + 800 + tid] = b_d2[tid];
    __syncthreads();

    for (int idx = tid; idx < 32 * 32; idx += NT) {
        int b = idx >> 5, j = idx & 31;
        int ob = b >> 3, bl = b & 7;
        float a = sm[HW_O + 768 + j];
        #pragma unroll 8
        for (int k = 0; k < 64; ++k) {
            float hv = sm[HA_O + (64 + k) * 32 + (((ob + k) & 3) << 3) + bl];
            a += hv * sm[XT_O + j * 64 + k];
        }
        sm[HA_O + b * 32 + j] = fmaxf(a, 0.f);
    }
    __syncthreads();
    for (int idx = tid; idx < 32 * 24; idx += NT) {
        int b = idx / 24, o = idx - b * 24;
        float a = sm[HW_O + 800 + o];
        #pragma unroll 8
        for (int j = 0; j < 32; ++j)
            a += sm[HA_O + b * 32 + j] * sm[HW_O + o * 32 + j];
        out[(size_t)(b0 + b) * 24 + o] = a;
    }
#endif
}

extern "C" void kernel_launch(void* const* d_in, const int* in_sizes, int n_in,
                              void* d_out, int out_size)
{
    const float* x     = (const float*)d_in[0];
    const float* W_ih1 = (const float*)d_in[1];
    const float* W_hh1 = (const float*)d_in[2];
    const float* b_ih1 = (const float*)d_in[3];
    const float* b_hh1 = (const float*)d_in[4];
    const float* W_ih2 = (const float*)d_in[5];
    const float* W_hh2 = (const float*)d_in[6];
    const float* b_ih2 = (const float*)d_in[7];
    const float* b_hh2 = (const float*)d_in[8];
    const float* W_d1  = (const float*)d_in[9];
    const float* b_d1  = (const float*)d_in[10];
    const float* W_d2  = (const float*)d_in[11];
    const float* b_d2  = (const float*)d_in[12];
    float* out = (float*)d_out;

    cudaFuncSetAttribute(lstm_kernel,
                         cudaFuncAttributeMaxDynamicSharedMemorySize, SM_BYTES_HOST);
    lstm_kernel<<<NBLK, NT, SM_BYTES_HOST>>>(
        x, W_ih1, W_hh1, b_ih1, b_hh1, W_ih2, W_hh2, b_ih2, b_hh2,
        W_d1, b_d1, W_d2, b_d2, out);
}